// round 1
// baseline (speedup 1.0000x reference)
#include <cuda_runtime.h>
#include <math.h>

// Problem constants
#define B_   512
#define T_   32
#define FIN  4096
#define L_   256
#define D_   256
#define M_   (B_*T_)        // 16384
#define KCONV (3*FIN)       // 12288

// Output layout (float32, concatenated in reference return order)
#define OFF_FEAT   0                         // (B,T,L)    4194304
#define OFF_ASSIGN 4194304                   // (B,T)      16384
#define OFF_SEG    4210688                   // (B,T)      16384
#define OFF_OUT    4227072                   // (B,2)      1024
#define OFF_AT     4228096                   // (B,1,T)    16384

// -------- scratch (device globals; no allocations allowed) --------
__device__ float g_Wt[KCONV * L_];       // repacked conv weight, [k][n]
__device__ float g_preV[M_ * D_];
__device__ float g_preU[M_ * D_];
__device__ float g_Amat[M_];
__device__ float g_bag[B_ * L_];
__device__ float g_h0[M_ * 256];
__device__ float g_h1[M_ * 128];

// ======================= weight repack =======================
// Wt[(tap*4096+c)*256 + l] = tsn_w[l*12288 + c*3 + tap]
__global__ void repack_w_kernel(const float* __restrict__ tsn_w, float* __restrict__ Wt) {
    int idx = blockIdx.x * blockDim.x + threadIdx.x;
    if (idx >= KCONV * L_) return;
    int n = idx & 255;
    int k = idx >> 8;
    int tap = k >> 12;
    int c = k & 4095;
    Wt[idx] = tsn_w[(size_t)n * 12288 + c * 3 + tap];
}

// ======================= generic SIMT GEMM =======================
// C[m][n] = act( sum_k A[m][k]*B[k][n] + bias[n] (+ exCol[m]*exW[n*exWs]) )
// CONV:   A is x with conv time-shift gather (K = 3*4096, tap = k>>12)
// TRANSB: B given as weight W[n][k] row-major with row stride ldb
// Tiles: BM=BN=128, BK=16, 256 threads, 8x8 micro-tile.
template<int CONV, int TRANSB, int RELU, int EXTRA>
__global__ void __launch_bounds__(256) gemm_k(
    const float* __restrict__ A, const float* __restrict__ Bw,
    const float* __restrict__ bias, float* __restrict__ C,
    int M, int N, int K, int ldb,
    const float* __restrict__ exCol, const float* __restrict__ exW, int exWs)
{
    __shared__ float As[16 * 132];   // [kc][row], padded stride 132
    __shared__ float Bs[16 * 128];   // [kc][n]

    const int m0 = blockIdx.y * 128;
    const int n0 = blockIdx.x * 128;
    const int tid = threadIdx.x;
    const int trow = (tid >> 4) * 8;
    const int tcol = (tid & 15) * 8;

    float acc[8][8];
#pragma unroll
    for (int i = 0; i < 8; i++)
#pragma unroll
        for (int j = 0; j < 8; j++) acc[i][j] = 0.f;

    for (int k0 = 0; k0 < K; k0 += 16) {
        // ---- load A tile (128 rows x 16 k) ----
#pragma unroll
        for (int s = 0; s < 2; s++) {
            int q = tid + s * 256;
            int row = q >> 2;
            int c4 = (q & 3) * 4;
            float4 v;
            if (CONV) {
                int m = m0 + row;
                int tap = k0 >> 12;
                int c = (k0 & 4095) + c4;
                int tt = (m & 31) + tap - 1;
                if (tt >= 0 && tt < 32) {
                    v = *reinterpret_cast<const float4*>(A + (size_t)(m + tap - 1) * 4096 + c);
                } else {
                    v = make_float4(0.f, 0.f, 0.f, 0.f);
                }
            } else {
                v = *reinterpret_cast<const float4*>(A + (size_t)(m0 + row) * K + k0 + c4);
            }
            As[(c4 + 0) * 132 + row] = v.x;
            As[(c4 + 1) * 132 + row] = v.y;
            As[(c4 + 2) * 132 + row] = v.z;
            As[(c4 + 3) * 132 + row] = v.w;
        }
        // ---- load B tile (16 k x 128 n) ----
        if (TRANSB) {
            int n = tid >> 1;
            int kh = (tid & 1) * 8;
            const float* bp = Bw + (size_t)(n0 + n) * ldb + k0 + kh;
#pragma unroll
            for (int j = 0; j < 8; j++) Bs[(kh + j) * 128 + n] = bp[j];
        } else {
            int kc = tid >> 4;
            int nn = (tid & 15) * 8;
            const float* bp = Bw + (size_t)(k0 + kc) * ldb + n0 + nn;
            float4 v0 = *reinterpret_cast<const float4*>(bp);
            float4 v1 = *reinterpret_cast<const float4*>(bp + 4);
            float* d = &Bs[kc * 128 + nn];
            d[0] = v0.x; d[1] = v0.y; d[2] = v0.z; d[3] = v0.w;
            d[4] = v1.x; d[5] = v1.y; d[6] = v1.z; d[7] = v1.w;
        }
        __syncthreads();
        // ---- compute ----
#pragma unroll
        for (int kc = 0; kc < 16; kc++) {
            float4 a0 = *reinterpret_cast<const float4*>(&As[kc * 132 + trow]);
            float4 a1 = *reinterpret_cast<const float4*>(&As[kc * 132 + trow + 4]);
            float4 b0 = *reinterpret_cast<const float4*>(&Bs[kc * 128 + tcol]);
            float4 b1 = *reinterpret_cast<const float4*>(&Bs[kc * 128 + tcol + 4]);
            float a[8] = {a0.x, a0.y, a0.z, a0.w, a1.x, a1.y, a1.z, a1.w};
            float b[8] = {b0.x, b0.y, b0.z, b0.w, b1.x, b1.y, b1.z, b1.w};
#pragma unroll
            for (int i = 0; i < 8; i++)
#pragma unroll
                for (int j = 0; j < 8; j++) acc[i][j] += a[i] * b[j];
        }
        __syncthreads();
    }

    // ---- epilogue ----
    float bv[8], ew[8];
#pragma unroll
    for (int j = 0; j < 8; j++) {
        bv[j] = bias[n0 + tcol + j];
        if (EXTRA) ew[j] = exW[(size_t)(n0 + tcol + j) * exWs];
    }
#pragma unroll
    for (int i = 0; i < 8; i++) {
        int m = m0 + trow + i;
        float ec = EXTRA ? exCol[m] : 0.f;
#pragma unroll
        for (int j = 0; j < 8; j++) {
            float v = acc[i][j] + bv[j];
            if (EXTRA) v += ec * ew[j];
            if (RELU) v = fmaxf(v, 0.f);
            C[(size_t)m * N + n0 + tcol + j] = v;
        }
    }
}

// ======================= gated attention combine =======================
// Amat[m] = sum_d tanh(preV) * sigmoid(preU) * gate_w[d] + gate_b
__global__ void __launch_bounds__(256) gated_kernel(
    const float* __restrict__ pv, const float* __restrict__ pu,
    const float* __restrict__ gw, const float* __restrict__ gb,
    float* __restrict__ Amat)
{
    int m = blockIdx.x * 8 + (threadIdx.x >> 5);
    int lane = threadIdx.x & 31;
    float acc = 0.f;
#pragma unroll
    for (int i = 0; i < 8; i++) {
        int d = lane + i * 32;
        float v = tanhf(pv[(size_t)m * 256 + d]);
        float u = 1.f / (1.f + expf(-pu[(size_t)m * 256 + d]));
        acc += v * u * gw[d];
    }
#pragma unroll
    for (int o = 16; o; o >>= 1) acc += __shfl_xor_sync(0xffffffffu, acc, o);
    if (lane == 0) Amat[m] = acc + gb[0];
}

// ======================= softmax over T, bag, At output =======================
__global__ void __launch_bounds__(256) softbag_kernel(
    const float* __restrict__ Amat, const float* __restrict__ feat,
    float* __restrict__ bag, float* __restrict__ outAt)
{
    __shared__ float p[32];
    int b = blockIdx.x;
    int tid = threadIdx.x;
    if (tid < 32) {
        float v = Amat[b * 32 + tid];
        outAt[b * 32 + tid] = v;   // At is the raw (pre-softmax) scores
        float mx = v;
#pragma unroll
        for (int o = 16; o; o >>= 1) mx = fmaxf(mx, __shfl_xor_sync(0xffffffffu, mx, o));
        float e = expf(v - mx);
        float s = e;
#pragma unroll
        for (int o = 16; o; o >>= 1) s += __shfl_xor_sync(0xffffffffu, s, o);
        p[tid] = e / s;
    }
    __syncthreads();
    float acc = 0.f;
#pragma unroll 8
    for (int t = 0; t < 32; t++) acc += p[t] * feat[(size_t)(b * 32 + t) * 256 + tid];
    bag[b * 256 + tid] = acc;
}

// ======================= bag classifier (256->256->128->32->1) =======================
__global__ void __launch_bounds__(256) bagclf_kernel(
    const float* __restrict__ bag,
    const float* __restrict__ w0, const float* __restrict__ b0,
    const float* __restrict__ w1, const float* __restrict__ b1,
    const float* __restrict__ w2, const float* __restrict__ b2,
    const float* __restrict__ w3, const float* __restrict__ b3,
    float* __restrict__ outp)
{
    __shared__ float sb[8 * 256];
    __shared__ float sh[8 * 256];
    int base = blockIdx.x * 8;
    int tid = threadIdx.x;
#pragma unroll
    for (int i = 0; i < 8; i++) sb[tid + i * 256] = bag[(size_t)base * 256 + tid + i * 256];
    __syncthreads();
    // layer 0: 256 -> 256
    {
        float acc[8] = {0, 0, 0, 0, 0, 0, 0, 0};
        const float* w = w0 + (size_t)tid * 256;
        for (int l = 0; l < 256; l++) {
            float wv = w[l];
#pragma unroll
            for (int r = 0; r < 8; r++) acc[r] += wv * sb[r * 256 + l];
        }
        float bb = b0[tid];
#pragma unroll
        for (int r = 0; r < 8; r++) sh[r * 256 + tid] = fmaxf(acc[r] + bb, 0.f);
    }
    __syncthreads();
    // layer 1: 256 -> 128
    if (tid < 128) {
        float acc[8] = {0, 0, 0, 0, 0, 0, 0, 0};
        const float* w = w1 + (size_t)tid * 256;
        for (int l = 0; l < 256; l++) {
            float wv = w[l];
#pragma unroll
            for (int r = 0; r < 8; r++) acc[r] += wv * sh[r * 256 + l];
        }
        float bb = b1[tid];
#pragma unroll
        for (int r = 0; r < 8; r++) sb[r * 128 + tid] = fmaxf(acc[r] + bb, 0.f);
    }
    __syncthreads();
    // layer 2: 128 -> 32
    if (tid < 32) {
        float acc[8] = {0, 0, 0, 0, 0, 0, 0, 0};
        const float* w = w2 + (size_t)tid * 128;
        for (int l = 0; l < 128; l++) {
            float wv = w[l];
#pragma unroll
            for (int r = 0; r < 8; r++) acc[r] += wv * sb[r * 128 + l];
        }
        float bb = b2[tid];
#pragma unroll
        for (int r = 0; r < 8; r++) sh[r * 32 + tid] = fmaxf(acc[r] + bb, 0.f);
    }
    __syncthreads();
    // final: 32 -> 1, sigmoid, *0.5 into output[:,0]
    if (tid < 8) {
        float a = 0.f;
        for (int j = 0; j < 32; j++) a += w3[j] * sh[tid * 32 + j];
        float o1 = 1.f / (1.f + expf(-(a + b3[0])));
        outp[(size_t)(base + tid) * 2 + 0] = 0.5f * o1;
    }
}

// ======================= seg tail (128 -> 32 -> 1, sigmoid) =======================
__global__ void __launch_bounds__(256) segtail_kernel(
    const float* __restrict__ h1,
    const float* __restrict__ w2, const float* __restrict__ b2,
    const float* __restrict__ w3, const float* __restrict__ b3,
    float* __restrict__ out_seg)
{
    __shared__ float sw2[128 * 32];  // transposed: [l][j]
    __shared__ float sh1[8 * 128];
    int m0 = blockIdx.x * 8;
    int tid = threadIdx.x;
#pragma unroll
    for (int i = 0; i < 16; i++) {
        int idx = tid + i * 256;
        int j = idx >> 7;
        int l = idx & 127;
        sw2[l * 32 + j] = w2[idx];
    }
#pragma unroll
    for (int i = 0; i < 4; i++) {
        int idx = tid + i * 256;
        sh1[idx] = h1[(size_t)m0 * 128 + idx];
    }
    __syncthreads();
    int r = tid >> 5, j = tid & 31;
    float acc = b2[j];
#pragma unroll 8
    for (int l = 0; l < 128; l++) acc += sw2[l * 32 + j] * sh1[r * 128 + l];
    float h2 = fmaxf(acc, 0.f);
    float v = h2 * w3[j];
#pragma unroll
    for (int o = 16; o; o >>= 1) v += __shfl_xor_sync(0xffffffffu, v, o);
    if (j == 0) out_seg[m0 + r] = 1.f / (1.f + expf(-(v + b3[0])));
}

// ======================= per-sample 2-means (cosine) + output2 =======================
__global__ void __launch_bounds__(256) kmeans_kernel(
    const float* __restrict__ feat, const float* __restrict__ seg,
    float* __restrict__ out_assign, float* __restrict__ out_pair)
{
    __shared__ float sf[32 * 256];
    __shared__ float sc[2 * 256];
    __shared__ float scn[2 * 256];
    __shared__ int sassign[32];
    __shared__ int s_ctrl[3];   // [0]=mask, [1]=stable, [2]=prev mask
    int b = blockIdx.x;
    int tid = threadIdx.x;
    int lane = tid & 31, w = tid >> 5;

#pragma unroll
    for (int i = 0; i < 32; i++) sf[tid + i * 256] = feat[(size_t)b * 8192 + tid + i * 256];
    // centers init: f[0], f[16] (each thread wrote sf[tid] and sf[4096+tid] itself)
    sc[tid] = sf[tid];
    sc[256 + tid] = sf[4096 + tid];
    if (tid == 0) s_ctrl[2] = 0;
    __syncthreads();

    int final_mask = 0;
    for (int it = 0; it < 100; it++) {
        // normalize centers (warps 0,1)
        if (w < 2) {
            float s = 0.f;
#pragma unroll
            for (int i = 0; i < 8; i++) {
                float v = sc[w * 256 + lane + i * 32];
                s += v * v;
            }
#pragma unroll
            for (int o = 16; o; o >>= 1) s += __shfl_xor_sync(0xffffffffu, s, o);
            float inv = 1.f / (sqrtf(s) + 1e-8f);
#pragma unroll
            for (int i = 0; i < 8; i++)
                scn[w * 256 + lane + i * 32] = sc[w * 256 + lane + i * 32] * inv;
        }
        __syncthreads();
        // similarity + assignment (warp w handles t = w*4+p).
        // Row scale of fn is positive & common to both centers -> comparison unaffected.
#pragma unroll
        for (int p = 0; p < 4; p++) {
            int t = w * 4 + p;
            float s0 = 0.f, s1 = 0.f;
#pragma unroll
            for (int i = 0; i < 8; i++) {
                float fv = sf[t * 256 + lane + i * 32];
                s0 += fv * scn[lane + i * 32];
                s1 += fv * scn[256 + lane + i * 32];
            }
#pragma unroll
            for (int o = 16; o; o >>= 1) {
                s0 += __shfl_xor_sync(0xffffffffu, s0, o);
                s1 += __shfl_xor_sync(0xffffffffu, s1, o);
            }
            if (lane == 0) sassign[t] = (s1 > s0) ? 1 : 0;
        }
        __syncthreads();
        if (tid == 0) {
            int mask = 0;
#pragma unroll
            for (int t = 0; t < 32; t++) mask |= sassign[t] << t;
            s_ctrl[0] = mask;
            s_ctrl[1] = (it > 0 && mask == s_ctrl[2]) ? 1 : 0;
            s_ctrl[2] = mask;
        }
        __syncthreads();
        int mask = s_ctrl[0];
        final_mask = mask;
        if (s_ctrl[1]) break;   // fixed point: remaining iterations are no-ops
        // update centers
        int cnt1 = __popc(mask);
        int cnt0 = 32 - cnt1;
        float a0 = 0.f, a1 = 0.f;
#pragma unroll
        for (int t = 0; t < 32; t++) {
            float fv = sf[t * 256 + tid];
            if ((mask >> t) & 1) a1 += fv; else a0 += fv;
        }
        if (cnt0 > 0) sc[tid] = a0 / (float)cnt0;
        if (cnt1 > 0) sc[256 + tid] = a1 / (float)cnt1;
        __syncthreads();
    }

    // outputs: assigns (as float) and output2*0.5 into output[:,1]
    if (tid < 32) {
        int bit = (final_mask >> tid) & 1;
        out_assign[b * 32 + tid] = (float)bit;
        float s = seg[b * 32 + tid];
        float v0 = bit ? 0.f : s;
        float v1 = bit ? s : 0.f;
#pragma unroll
        for (int o = 16; o; o >>= 1) {
            v0 += __shfl_xor_sync(0xffffffffu, v0, o);
            v1 += __shfl_xor_sync(0xffffffffu, v1, o);
        }
        int cnt1 = __popc(final_mask);
        int cnt0 = 32 - cnt1;
        float m0 = (cnt0 > 0) ? v0 / (float)cnt0 : -INFINITY;
        float m1 = (cnt1 > 0) ? v1 / (float)cnt1 : -INFINITY;
        if (tid == 0) out_pair[(size_t)b * 2 + 1] = 0.5f * fmaxf(m0, m1);
    }
}

// ======================= launch =======================
extern "C" void kernel_launch(void* const* d_in, const int* in_sizes, int n_in,
                              void* d_out, int out_size)
{
    const float* x      = (const float*)d_in[0];
    const float* tsn_w  = (const float*)d_in[1];
    const float* tsn_b  = (const float*)d_in[2];
    const float* aV_w   = (const float*)d_in[3];
    const float* aV_b   = (const float*)d_in[4];
    const float* aU_w   = (const float*)d_in[5];
    const float* aU_b   = (const float*)d_in[6];
    const float* gate_w = (const float*)d_in[7];
    const float* gate_b = (const float*)d_in[8];
    const float* cb_w0  = (const float*)d_in[9];
    const float* cb_b0  = (const float*)d_in[10];
    const float* cb_w1  = (const float*)d_in[11];
    const float* cb_b1  = (const float*)d_in[12];
    const float* cb_w2  = (const float*)d_in[13];
    const float* cb_b2  = (const float*)d_in[14];
    const float* cb_w3  = (const float*)d_in[15];
    const float* cb_b3  = (const float*)d_in[16];
    const float* cs_w0  = (const float*)d_in[17];
    const float* cs_b0  = (const float*)d_in[18];
    const float* cs_w1  = (const float*)d_in[19];
    const float* cs_b1  = (const float*)d_in[20];
    const float* cs_w2  = (const float*)d_in[21];
    const float* cs_b2  = (const float*)d_in[22];
    const float* cs_w3  = (const float*)d_in[23];
    const float* cs_b3  = (const float*)d_in[24];

    float* out = (float*)d_out;
    float* feat    = out + OFF_FEAT;
    float* oAssign = out + OFF_ASSIGN;
    float* oSeg    = out + OFF_SEG;
    float* oOut    = out + OFF_OUT;
    float* oAt     = out + OFF_AT;

    float *Wt, *preV, *preU, *Amat, *bag, *h0, *h1;
    cudaGetSymbolAddress((void**)&Wt,   g_Wt);
    cudaGetSymbolAddress((void**)&preV, g_preV);
    cudaGetSymbolAddress((void**)&preU, g_preU);
    cudaGetSymbolAddress((void**)&Amat, g_Amat);
    cudaGetSymbolAddress((void**)&bag,  g_bag);
    cudaGetSymbolAddress((void**)&h0,   g_h0);
    cudaGetSymbolAddress((void**)&h1,   g_h1);

    // 1) repack conv weight to [k][n]
    repack_w_kernel<<<(KCONV * L_ + 255) / 256, 256>>>(tsn_w, Wt);

    // 2) conv-as-GEMM -> feature (output region, reused downstream)
    gemm_k<1, 0, 0, 0><<<dim3(2, 128), 256>>>(x, Wt, tsn_b, feat,
                                              M_, 256, KCONV, 256, nullptr, nullptr, 0);

    // 3) attention projections V and U
    gemm_k<0, 1, 0, 0><<<dim3(2, 128), 256>>>(feat, aV_w, aV_b, preV,
                                              M_, 256, 256, 256, nullptr, nullptr, 0);
    gemm_k<0, 1, 0, 0><<<dim3(2, 128), 256>>>(feat, aU_w, aU_b, preU,
                                              M_, 256, 256, 256, nullptr, nullptr, 0);

    // 4) gated combine -> Amat
    gated_kernel<<<M_ / 8, 256>>>(preV, preU, gate_w, gate_b, Amat);

    // 5) softmax over T + bag + At output
    softbag_kernel<<<B_, 256>>>(Amat, feat, bag, oAt);

    // 6) bag classifier -> output[:,0]
    bagclf_kernel<<<B_ / 8, 256>>>(bag, cb_w0, cb_b0, cb_w1, cb_b1,
                                   cb_w2, cb_b2, cb_w3, cb_b3, oOut);

    // 7) seg classifier: h0 (K=256 + rank-1 extra col), h1, tail -> output_seg
    gemm_k<0, 1, 1, 1><<<dim3(2, 128), 256>>>(feat, cs_w0, cs_b0, h0,
                                              M_, 256, 256, 257, Amat, cs_w0 + 256, 257);
    gemm_k<0, 1, 1, 0><<<dim3(1, 128), 256>>>(h0, cs_w1, cs_b1, h1,
                                              M_, 128, 256, 256, nullptr, nullptr, 0);
    segtail_kernel<<<M_ / 8, 256>>>(h1, cs_w2, cs_b2, cs_w3, cs_b3, oSeg);

    // 8) 2-means (cosine, early-exit fixed point) -> assigns + output[:,1]
    kmeans_kernel<<<B_, 256>>>(feat, oSeg, oAssign, oOut);
}

// round 2
// speedup vs baseline: 1.0003x; 1.0003x over previous
#include <cuda_runtime.h>
#include <math.h>

// Problem constants
#define B_   512
#define T_   32
#define FIN  4096
#define L_   256
#define D_   256
#define M_   (B_*T_)        // 16384
#define KCONV (3*FIN)       // 12288

// Output layout (float32, concatenated in reference return order)
#define OFF_FEAT   0                         // (B,T,L)    4194304
#define OFF_ASSIGN 4194304                   // (B,T)      16384
#define OFF_SEG    4210688                   // (B,T)      16384
#define OFF_OUT    4227072                   // (B,2)      1024
#define OFF_AT     4228096                   // (B,1,T)    16384

// -------- scratch (device globals; no allocations allowed) --------
__device__ float g_Wt[KCONV * L_];       // repacked conv weight, [k][n]
__device__ float g_preV[M_ * D_];
__device__ float g_preU[M_ * D_];
__device__ float g_Amat[M_];
__device__ float g_bag[B_ * L_];
__device__ float g_h0[M_ * 256];
__device__ float g_h1[M_ * 128];

// ======================= weight repack =======================
// Wt[(tap*4096+c)*256 + l] = tsn_w[l*12288 + c*3 + tap]
__global__ void repack_w_kernel(const float* __restrict__ tsn_w, float* __restrict__ Wt) {
    int idx = blockIdx.x * blockDim.x + threadIdx.x;
    if (idx >= KCONV * L_) return;
    int n = idx & 255;
    int k = idx >> 8;
    int tap = k >> 12;
    int c = k & 4095;
    Wt[idx] = tsn_w[(size_t)n * 12288 + c * 3 + tap];
}

// ======================= generic SIMT GEMM =======================
// C[m][n] = act( sum_k A[m][k]*B[k][n] + bias[n] (+ exCol[m]*exW[n*exWs]) )
// CONV:   A is x with conv time-shift gather (K = 3*4096, tap = k>>12)
// TRANSB: B given as weight W[n][k] row-major with row stride ldb
// Tiles: BM=BN=128, BK=16, 256 threads, 8x8 micro-tile.
template<int CONV, int TRANSB, int RELU, int EXTRA>
__global__ void __launch_bounds__(256) gemm_k(
    const float* __restrict__ A, const float* __restrict__ Bw,
    const float* __restrict__ bias, float* __restrict__ C,
    int M, int N, int K, int ldb,
    const float* __restrict__ exCol, const float* __restrict__ exW, int exWs)
{
    __shared__ float As[16 * 132];   // [kc][row], padded stride 132
    __shared__ float Bs[16 * 128];   // [kc][n]

    const int m0 = blockIdx.y * 128;
    const int n0 = blockIdx.x * 128;
    const int tid = threadIdx.x;
    const int trow = (tid >> 4) * 8;
    const int tcol = (tid & 15) * 8;

    float acc[8][8];
#pragma unroll
    for (int i = 0; i < 8; i++)
#pragma unroll
        for (int j = 0; j < 8; j++) acc[i][j] = 0.f;

    for (int k0 = 0; k0 < K; k0 += 16) {
        // ---- load A tile (128 rows x 16 k) ----
#pragma unroll
        for (int s = 0; s < 2; s++) {
            int q = tid + s * 256;
            int row = q >> 2;
            int c4 = (q & 3) * 4;
            float4 v;
            if (CONV) {
                int m = m0 + row;
                int tap = k0 >> 12;
                int c = (k0 & 4095) + c4;
                int tt = (m & 31) + tap - 1;
                if (tt >= 0 && tt < 32) {
                    v = *reinterpret_cast<const float4*>(A + (size_t)(m + tap - 1) * 4096 + c);
                } else {
                    v = make_float4(0.f, 0.f, 0.f, 0.f);
                }
            } else {
                v = *reinterpret_cast<const float4*>(A + (size_t)(m0 + row) * K + k0 + c4);
            }
            As[(c4 + 0) * 132 + row] = v.x;
            As[(c4 + 1) * 132 + row] = v.y;
            As[(c4 + 2) * 132 + row] = v.z;
            As[(c4 + 3) * 132 + row] = v.w;
        }
        // ---- load B tile (16 k x 128 n) ----
        if (TRANSB) {
            int n = tid >> 1;
            int kh = (tid & 1) * 8;
            const float* bp = Bw + (size_t)(n0 + n) * ldb + k0 + kh;
#pragma unroll
            for (int j = 0; j < 8; j++) Bs[(kh + j) * 128 + n] = bp[j];
        } else {
            int kc = tid >> 4;
            int nn = (tid & 15) * 8;
            const float* bp = Bw + (size_t)(k0 + kc) * ldb + n0 + nn;
            float4 v0 = *reinterpret_cast<const float4*>(bp);
            float4 v1 = *reinterpret_cast<const float4*>(bp + 4);
            float* d = &Bs[kc * 128 + nn];
            d[0] = v0.x; d[1] = v0.y; d[2] = v0.z; d[3] = v0.w;
            d[4] = v1.x; d[5] = v1.y; d[6] = v1.z; d[7] = v1.w;
        }
        __syncthreads();
        // ---- compute ----
#pragma unroll
        for (int kc = 0; kc < 16; kc++) {
            float4 a0 = *reinterpret_cast<const float4*>(&As[kc * 132 + trow]);
            float4 a1 = *reinterpret_cast<const float4*>(&As[kc * 132 + trow + 4]);
            float4 b0 = *reinterpret_cast<const float4*>(&Bs[kc * 128 + tcol]);
            float4 b1 = *reinterpret_cast<const float4*>(&Bs[kc * 128 + tcol + 4]);
            float a[8] = {a0.x, a0.y, a0.z, a0.w, a1.x, a1.y, a1.z, a1.w};
            float b[8] = {b0.x, b0.y, b0.z, b0.w, b1.x, b1.y, b1.z, b1.w};
#pragma unroll
            for (int i = 0; i < 8; i++)
#pragma unroll
                for (int j = 0; j < 8; j++) acc[i][j] += a[i] * b[j];
        }
        __syncthreads();
    }

    // ---- epilogue ----
    float bv[8], ew[8];
#pragma unroll
    for (int j = 0; j < 8; j++) {
        bv[j] = bias[n0 + tcol + j];
        if (EXTRA) ew[j] = exW[(size_t)(n0 + tcol + j) * exWs];
    }
#pragma unroll
    for (int i = 0; i < 8; i++) {
        int m = m0 + trow + i;
        float ec = EXTRA ? exCol[m] : 0.f;
#pragma unroll
        for (int j = 0; j < 8; j++) {
            float v = acc[i][j] + bv[j];
            if (EXTRA) v += ec * ew[j];
            if (RELU) v = fmaxf(v, 0.f);
            C[(size_t)m * N + n0 + tcol + j] = v;
        }
    }
}

// ======================= gated attention combine =======================
// Amat[m] = sum_d tanh(preV) * sigmoid(preU) * gate_w[d] + gate_b
__global__ void __launch_bounds__(256) gated_kernel(
    const float* __restrict__ pv, const float* __restrict__ pu,
    const float* __restrict__ gw, const float* __restrict__ gb,
    float* __restrict__ Amat)
{
    int m = blockIdx.x * 8 + (threadIdx.x >> 5);
    int lane = threadIdx.x & 31;
    float acc = 0.f;
#pragma unroll
    for (int i = 0; i < 8; i++) {
        int d = lane + i * 32;
        float v = tanhf(pv[(size_t)m * 256 + d]);
        float u = 1.f / (1.f + expf(-pu[(size_t)m * 256 + d]));
        acc += v * u * gw[d];
    }
#pragma unroll
    for (int o = 16; o; o >>= 1) acc += __shfl_xor_sync(0xffffffffu, acc, o);
    if (lane == 0) Amat[m] = acc + gb[0];
}

// ======================= softmax over T, bag, At output =======================
__global__ void __launch_bounds__(256) softbag_kernel(
    const float* __restrict__ Amat, const float* __restrict__ feat,
    float* __restrict__ bag, float* __restrict__ outAt)
{
    __shared__ float p[32];
    int b = blockIdx.x;
    int tid = threadIdx.x;
    if (tid < 32) {
        float v = Amat[b * 32 + tid];
        outAt[b * 32 + tid] = v;   // At is the raw (pre-softmax) scores
        float mx = v;
#pragma unroll
        for (int o = 16; o; o >>= 1) mx = fmaxf(mx, __shfl_xor_sync(0xffffffffu, mx, o));
        float e = expf(v - mx);
        float s = e;
#pragma unroll
        for (int o = 16; o; o >>= 1) s += __shfl_xor_sync(0xffffffffu, s, o);
        p[tid] = e / s;
    }
    __syncthreads();
    float acc = 0.f;
#pragma unroll 8
    for (int t = 0; t < 32; t++) acc += p[t] * feat[(size_t)(b * 32 + t) * 256 + tid];
    bag[b * 256 + tid] = acc;
}

// ======================= bag classifier (256->256->128->32->1) =======================
__global__ void __launch_bounds__(256) bagclf_kernel(
    const float* __restrict__ bag,
    const float* __restrict__ w0, const float* __restrict__ b0,
    const float* __restrict__ w1, const float* __restrict__ b1,
    const float* __restrict__ w2, const float* __restrict__ b2,
    const float* __restrict__ w3, const float* __restrict__ b3,
    float* __restrict__ outp)
{
    __shared__ float sb[8 * 256];
    __shared__ float sh[8 * 256];
    int base = blockIdx.x * 8;
    int tid = threadIdx.x;
#pragma unroll
    for (int i = 0; i < 8; i++) sb[tid + i * 256] = bag[(size_t)base * 256 + tid + i * 256];
    __syncthreads();
    // layer 0: 256 -> 256
    {
        float acc[8] = {0, 0, 0, 0, 0, 0, 0, 0};
        const float* w = w0 + (size_t)tid * 256;
        for (int l = 0; l < 256; l++) {
            float wv = w[l];
#pragma unroll
            for (int r = 0; r < 8; r++) acc[r] += wv * sb[r * 256 + l];
        }
        float bb = b0[tid];
#pragma unroll
        for (int r = 0; r < 8; r++) sh[r * 256 + tid] = fmaxf(acc[r] + bb, 0.f);
    }
    __syncthreads();
    // layer 1: 256 -> 128
    if (tid < 128) {
        float acc[8] = {0, 0, 0, 0, 0, 0, 0, 0};
        const float* w = w1 + (size_t)tid * 256;
        for (int l = 0; l < 256; l++) {
            float wv = w[l];
#pragma unroll
            for (int r = 0; r < 8; r++) acc[r] += wv * sh[r * 256 + l];
        }
        float bb = b1[tid];
#pragma unroll
        for (int r = 0; r < 8; r++) sb[r * 128 + tid] = fmaxf(acc[r] + bb, 0.f);
    }
    __syncthreads();
    // layer 2: 128 -> 32
    if (tid < 32) {
        float acc[8] = {0, 0, 0, 0, 0, 0, 0, 0};
        const float* w = w2 + (size_t)tid * 128;
        for (int l = 0; l < 128; l++) {
            float wv = w[l];
#pragma unroll
            for (int r = 0; r < 8; r++) acc[r] += wv * sb[r * 128 + l];
        }
        float bb = b2[tid];
#pragma unroll
        for (int r = 0; r < 8; r++) sh[r * 32 + tid] = fmaxf(acc[r] + bb, 0.f);
    }
    __syncthreads();
    // final: 32 -> 1, sigmoid, *0.5 into output[:,0]
    if (tid < 8) {
        float a = 0.f;
        for (int j = 0; j < 32; j++) a += w3[j] * sh[tid * 32 + j];
        float o1 = 1.f / (1.f + expf(-(a + b3[0])));
        outp[(size_t)(base + tid) * 2 + 0] = 0.5f * o1;
    }
}

// ======================= seg tail (128 -> 32 -> 1, sigmoid) =======================
__global__ void __launch_bounds__(256) segtail_kernel(
    const float* __restrict__ h1,
    const float* __restrict__ w2, const float* __restrict__ b2,
    const float* __restrict__ w3, const float* __restrict__ b3,
    float* __restrict__ out_seg)
{
    __shared__ float sw2[128 * 32];  // transposed: [l][j]
    __shared__ float sh1[8 * 128];
    int m0 = blockIdx.x * 8;
    int tid = threadIdx.x;
#pragma unroll
    for (int i = 0; i < 16; i++) {
        int idx = tid + i * 256;
        int j = idx >> 7;
        int l = idx & 127;
        sw2[l * 32 + j] = w2[idx];
    }
#pragma unroll
    for (int i = 0; i < 4; i++) {
        int idx = tid + i * 256;
        sh1[idx] = h1[(size_t)m0 * 128 + idx];
    }
    __syncthreads();
    int r = tid >> 5, j = tid & 31;
    float acc = b2[j];
#pragma unroll 8
    for (int l = 0; l < 128; l++) acc += sw2[l * 32 + j] * sh1[r * 128 + l];
    float h2 = fmaxf(acc, 0.f);
    float v = h2 * w3[j];
#pragma unroll
    for (int o = 16; o; o >>= 1) v += __shfl_xor_sync(0xffffffffu, v, o);
    if (j == 0) out_seg[m0 + r] = 1.f / (1.f + expf(-(v + b3[0])));
}

// ======================= per-sample 2-means (cosine) + output2 =======================
__global__ void __launch_bounds__(256) kmeans_kernel(
    const float* __restrict__ feat, const float* __restrict__ seg,
    float* __restrict__ out_assign, float* __restrict__ out_pair)
{
    __shared__ float sf[32 * 256];
    __shared__ float sc[2 * 256];
    __shared__ float scn[2 * 256];
    __shared__ int sassign[32];
    __shared__ int s_ctrl[3];   // [0]=mask, [1]=stable, [2]=prev mask
    int b = blockIdx.x;
    int tid = threadIdx.x;
    int lane = tid & 31, w = tid >> 5;

#pragma unroll
    for (int i = 0; i < 32; i++) sf[tid + i * 256] = feat[(size_t)b * 8192 + tid + i * 256];
    // centers init: f[0], f[16] (each thread wrote sf[tid] and sf[4096+tid] itself)
    sc[tid] = sf[tid];
    sc[256 + tid] = sf[4096 + tid];
    if (tid == 0) s_ctrl[2] = 0;
    __syncthreads();

    int final_mask = 0;
    for (int it = 0; it < 100; it++) {
        // normalize centers (warps 0,1)
        if (w < 2) {
            float s = 0.f;
#pragma unroll
            for (int i = 0; i < 8; i++) {
                float v = sc[w * 256 + lane + i * 32];
                s += v * v;
            }
#pragma unroll
            for (int o = 16; o; o >>= 1) s += __shfl_xor_sync(0xffffffffu, s, o);
            float inv = 1.f / (sqrtf(s) + 1e-8f);
#pragma unroll
            for (int i = 0; i < 8; i++)
                scn[w * 256 + lane + i * 32] = sc[w * 256 + lane + i * 32] * inv;
        }
        __syncthreads();
        // similarity + assignment (warp w handles t = w*4+p).
        // Row scale of fn is positive & common to both centers -> comparison unaffected.
#pragma unroll
        for (int p = 0; p < 4; p++) {
            int t = w * 4 + p;
            float s0 = 0.f, s1 = 0.f;
#pragma unroll
            for (int i = 0; i < 8; i++) {
                float fv = sf[t * 256 + lane + i * 32];
                s0 += fv * scn[lane + i * 32];
                s1 += fv * scn[256 + lane + i * 32];
            }
#pragma unroll
            for (int o = 16; o; o >>= 1) {
                s0 += __shfl_xor_sync(0xffffffffu, s0, o);
                s1 += __shfl_xor_sync(0xffffffffu, s1, o);
            }
            if (lane == 0) sassign[t] = (s1 > s0) ? 1 : 0;
        }
        __syncthreads();
        if (tid == 0) {
            int mask = 0;
#pragma unroll
            for (int t = 0; t < 32; t++) mask |= sassign[t] << t;
            s_ctrl[0] = mask;
            s_ctrl[1] = (it > 0 && mask == s_ctrl[2]) ? 1 : 0;
            s_ctrl[2] = mask;
        }
        __syncthreads();
        int mask = s_ctrl[0];
        final_mask = mask;
        if (s_ctrl[1]) break;   // fixed point: remaining iterations are no-ops
        // update centers
        int cnt1 = __popc(mask);
        int cnt0 = 32 - cnt1;
        float a0 = 0.f, a1 = 0.f;
#pragma unroll
        for (int t = 0; t < 32; t++) {
            float fv = sf[t * 256 + tid];
            if ((mask >> t) & 1) a1 += fv; else a0 += fv;
        }
        if (cnt0 > 0) sc[tid] = a0 / (float)cnt0;
        if (cnt1 > 0) sc[256 + tid] = a1 / (float)cnt1;
        __syncthreads();
    }

    // outputs: assigns (as float) and output2*0.5 into output[:,1]
    if (tid < 32) {
        int bit = (final_mask >> tid) & 1;
        out_assign[b * 32 + tid] = (float)bit;
        float s = seg[b * 32 + tid];
        float v0 = bit ? 0.f : s;
        float v1 = bit ? s : 0.f;
#pragma unroll
        for (int o = 16; o; o >>= 1) {
            v0 += __shfl_xor_sync(0xffffffffu, v0, o);
            v1 += __shfl_xor_sync(0xffffffffu, v1, o);
        }
        int cnt1 = __popc(final_mask);
        int cnt0 = 32 - cnt1;
        float m0 = (cnt0 > 0) ? v0 / (float)cnt0 : -INFINITY;
        float m1 = (cnt1 > 0) ? v1 / (float)cnt1 : -INFINITY;
        if (tid == 0) out_pair[(size_t)b * 2 + 1] = 0.5f * fmaxf(m0, m1);
    }
}

// ======================= launch =======================
extern "C" void kernel_launch(void* const* d_in, const int* in_sizes, int n_in,
                              void* d_out, int out_size)
{
    const float* x      = (const float*)d_in[0];
    const float* tsn_w  = (const float*)d_in[1];
    const float* tsn_b  = (const float*)d_in[2];
    const float* aV_w   = (const float*)d_in[3];
    const float* aV_b   = (const float*)d_in[4];
    const float* aU_w   = (const float*)d_in[5];
    const float* aU_b   = (const float*)d_in[6];
    const float* gate_w = (const float*)d_in[7];
    const float* gate_b = (const float*)d_in[8];
    const float* cb_w0  = (const float*)d_in[9];
    const float* cb_b0  = (const float*)d_in[10];
    const float* cb_w1  = (const float*)d_in[11];
    const float* cb_b1  = (const float*)d_in[12];
    const float* cb_w2  = (const float*)d_in[13];
    const float* cb_b2  = (const float*)d_in[14];
    const float* cb_w3  = (const float*)d_in[15];
    const float* cb_b3  = (const float*)d_in[16];
    const float* cs_w0  = (const float*)d_in[17];
    const float* cs_b0  = (const float*)d_in[18];
    const float* cs_w1  = (const float*)d_in[19];
    const float* cs_b1  = (const float*)d_in[20];
    const float* cs_w2  = (const float*)d_in[21];
    const float* cs_b2  = (const float*)d_in[22];
    const float* cs_w3  = (const float*)d_in[23];
    const float* cs_b3  = (const float*)d_in[24];

    float* out = (float*)d_out;
    float* feat    = out + OFF_FEAT;
    float* oAssign = out + OFF_ASSIGN;
    float* oSeg    = out + OFF_SEG;
    float* oOut    = out + OFF_OUT;
    float* oAt     = out + OFF_AT;

    float *Wt, *preV, *preU, *Amat, *bag, *h0, *h1;
    cudaGetSymbolAddress((void**)&Wt,   g_Wt);
    cudaGetSymbolAddress((void**)&preV, g_preV);
    cudaGetSymbolAddress((void**)&preU, g_preU);
    cudaGetSymbolAddress((void**)&Amat, g_Amat);
    cudaGetSymbolAddress((void**)&bag,  g_bag);
    cudaGetSymbolAddress((void**)&h0,   g_h0);
    cudaGetSymbolAddress((void**)&h1,   g_h1);

    // 1) repack conv weight to [k][n]
    repack_w_kernel<<<(KCONV * L_ + 255) / 256, 256>>>(tsn_w, Wt);

    // 2) conv-as-GEMM -> feature (output region, reused downstream)
    gemm_k<1, 0, 0, 0><<<dim3(2, 128), 256>>>(x, Wt, tsn_b, feat,
                                              M_, 256, KCONV, 256, nullptr, nullptr, 0);

    // 3) attention projections V and U
    gemm_k<0, 1, 0, 0><<<dim3(2, 128), 256>>>(feat, aV_w, aV_b, preV,
                                              M_, 256, 256, 256, nullptr, nullptr, 0);
    gemm_k<0, 1, 0, 0><<<dim3(2, 128), 256>>>(feat, aU_w, aU_b, preU,
                                              M_, 256, 256, 256, nullptr, nullptr, 0);

    // 4) gated combine -> Amat
    gated_kernel<<<M_ / 8, 256>>>(preV, preU, gate_w, gate_b, Amat);

    // 5) softmax over T + bag + At output
    softbag_kernel<<<B_, 256>>>(Amat, feat, bag, oAt);

    // 6) bag classifier -> output[:,0]
    bagclf_kernel<<<B_ / 8, 256>>>(bag, cb_w0, cb_b0, cb_w1, cb_b1,
                                   cb_w2, cb_b2, cb_w3, cb_b3, oOut);

    // 7) seg classifier: h0 (K=256 + rank-1 extra col), h1, tail -> output_seg
    gemm_k<0, 1, 1, 1><<<dim3(2, 128), 256>>>(feat, cs_w0, cs_b0, h0,
                                              M_, 256, 256, 257, Amat, cs_w0 + 256, 257);
    gemm_k<0, 1, 1, 0><<<dim3(1, 128), 256>>>(h0, cs_w1, cs_b1, h1,
                                              M_, 128, 256, 256, nullptr, nullptr, 0);
    segtail_kernel<<<M_ / 8, 256>>>(h1, cs_w2, cs_b2, cs_w3, cs_b3, oSeg);

    // 8) 2-means (cosine, early-exit fixed point) -> assigns + output[:,1]
    kmeans_kernel<<<B_, 256>>>(feat, oSeg, oAssign, oOut);
}

// round 4
// speedup vs baseline: 1.5019x; 1.5015x over previous
#include <cuda_runtime.h>
#include <cuda_bf16.h>
#include <math.h>
#include <stdint.h>

#define B_   512
#define T_   32
#define FIN  4096
#define L_   256
#define M_   (B_*T_)
#define KCONV (3*FIN)

#define OFF_FEAT   0
#define OFF_ASSIGN 4194304
#define OFF_SEG    4210688
#define OFF_OUT    4227072
#define OFF_AT     4228096

// -------- scratch (device globals) --------
__device__ __align__(16) __nv_bfloat16 g_xhi[(size_t)M_ * FIN];
__device__ __align__(16) __nv_bfloat16 g_xlo[(size_t)M_ * FIN];
__device__ __align__(16) __nv_bfloat16 g_wthi[(size_t)L_ * KCONV];
__device__ __align__(16) __nv_bfloat16 g_wtlo[(size_t)L_ * KCONV];
__device__ __align__(16) __nv_bfloat16 g_bwh[229376];   // aV|aU|cs0|cs1 as [n][256]
__device__ __align__(16) __nv_bfloat16 g_bwl[229376];
__device__ __align__(16) __nv_bfloat16 g_fhi[(size_t)M_ * L_];
__device__ __align__(16) __nv_bfloat16 g_flo[(size_t)M_ * L_];
__device__ __align__(16) __nv_bfloat16 g_h0hi[(size_t)M_ * 256];
__device__ __align__(16) __nv_bfloat16 g_h0lo[(size_t)M_ * 256];
__device__ float g_preV[(size_t)M_ * 256];
__device__ float g_preU[(size_t)M_ * 256];
__device__ float g_Amat[M_];
__device__ float g_bag[B_ * L_];
__device__ float g_h1[(size_t)M_ * 128];

// ======================= helpers =======================
__device__ __forceinline__ void splitbf(float v, __nv_bfloat16& h, __nv_bfloat16& l) {
    h = __float2bfloat16(v);
    l = __float2bfloat16(v - __bfloat162float(h));
}
__device__ __forceinline__ uint32_t smem_u32(const void* p) {
    uint32_t a;
    asm("{ .reg .u64 t; cvta.to.shared.u64 t, %1; cvt.u32.u64 %0, t; }" : "=r"(a) : "l"(p));
    return a;
}
__device__ __forceinline__ void cp16(uint32_t dst, const void* src, uint32_t sz) {
    asm volatile("cp.async.cg.shared.global [%0], [%1], 16, %2;"
                 :: "r"(dst), "l"(src), "r"(sz) : "memory");
}
__device__ __forceinline__ void ldm4(uint32_t* r, uint32_t addr) {
    asm volatile("ldmatrix.sync.aligned.m8n8.x4.shared.b16 {%0,%1,%2,%3}, [%4];"
                 : "=r"(r[0]), "=r"(r[1]), "=r"(r[2]), "=r"(r[3]) : "r"(addr));
}
__device__ __forceinline__ void mma16816(float* c, const uint32_t* a, const uint32_t* b) {
    asm volatile("mma.sync.aligned.m16n8k16.row.col.f32.bf16.bf16.f32 "
                 "{%0,%1,%2,%3}, {%4,%5,%6,%7}, {%8,%9}, {%0,%1,%2,%3};"
                 : "+f"(c[0]), "+f"(c[1]), "+f"(c[2]), "+f"(c[3])
                 : "r"(a[0]), "r"(a[1]), "r"(a[2]), "r"(a[3]), "r"(b[0]), "r"(b[1]));
}

// ======================= split / repack kernels =======================
__global__ void split_x_k(const float4* __restrict__ x,
                          __nv_bfloat162* __restrict__ hi, __nv_bfloat162* __restrict__ lo) {
    size_t i = (size_t)blockIdx.x * 256 + threadIdx.x;
    float4 v = x[i];
    __nv_bfloat16 h[4], l[4];
    splitbf(v.x, h[0], l[0]); splitbf(v.y, h[1], l[1]);
    splitbf(v.z, h[2], l[2]); splitbf(v.w, h[3], l[3]);
    __nv_bfloat162 a, b, c, d;
    a.x = h[0]; a.y = h[1]; b.x = h[2]; b.y = h[3];
    c.x = l[0]; c.y = l[1]; d.x = l[2]; d.y = l[3];
    hi[2 * i] = a; hi[2 * i + 1] = b;
    lo[2 * i] = c; lo[2 * i + 1] = d;
}

__global__ void splitw_conv_k(const float* __restrict__ w,
                              __nv_bfloat16* __restrict__ hi, __nv_bfloat16* __restrict__ lo) {
    int idx = blockIdx.x * 256 + threadIdx.x;          // [n][k], k = tap*4096 + c
    int n = idx / KCONV;
    int k = idx - n * KCONV;
    int tap = k >> 12, c = k & 4095;
    float v = w[(size_t)n * KCONV + c * 3 + tap];
    __nv_bfloat16 h, l; splitbf(v, h, l);
    hi[idx] = h; lo[idx] = l;
}

__global__ void splitw_gen_k(const float* __restrict__ w, int srcStride, int total,
                             __nv_bfloat16* __restrict__ hi, __nv_bfloat16* __restrict__ lo) {
    int idx = blockIdx.x * 256 + threadIdx.x;
    if (idx >= total) return;
    int n = idx >> 8, k = idx & 255;
    float v = w[(size_t)n * srcStride + k];
    __nv_bfloat16 h, l; splitbf(v, h, l);
    hi[idx] = h; lo[idx] = l;
}

// ======================= HMMA GEMM (mma.sync bf16, 3-pass hi/lo) =======================
// D[m][n] = epi( sum_k A[m][k]*B[n][k] + bias[n] )
// CTA tile 128x128, BK=64, 256 threads (8 warps, warp tile 64x32), cp.async 2-stage.
// EPI: 0=bias, write fp32 + bf16 hi/lo  (conv -> feature)
//      1=bias, write fp32               (preV / preU)
//      2=relu(bias + exCol[m]*exW[n*257]), write bf16 hi/lo  (seg layer0)
//      3=relu(bias), write fp32         (seg layer1)
#define ST 65536
template<int CONV, int EPI>
__global__ void __launch_bounds__(256) mm_gemm(
    const __nv_bfloat16* __restrict__ Ahi, const __nv_bfloat16* __restrict__ Alo, int ldA,
    const __nv_bfloat16* __restrict__ Bhi, const __nv_bfloat16* __restrict__ Blo, int ldB,
    const float* __restrict__ bias, const float* __restrict__ exCol,
    const float* __restrict__ exW,
    float* __restrict__ Cf, __nv_bfloat16* __restrict__ Chi, __nv_bfloat16* __restrict__ Clo,
    int N, int K)
{
    extern __shared__ __align__(128) char smem[];
    const int tid = threadIdx.x;
    const int m0 = blockIdx.y * 128;
    const int n0 = blockIdx.x * 128;
    const uint32_t sb = smem_u32(smem);
    const int NCH = K >> 6;

    const int lane = tid & 31, warp = tid >> 5;
    const int wm = (warp >> 2) * 64, wn = (warp & 3) * 32;
    const int rsel = lane & 15, ksel = lane >> 4;

    float acc[4][4][4];
#pragma unroll
    for (int i = 0; i < 4; i++)
#pragma unroll
        for (int j = 0; j < 4; j++)
#pragma unroll
            for (int u = 0; u < 4; u++) acc[i][j][u] = 0.f;

    // ---- loader lambda-ish macro via explicit code ----
    auto issue_load = [&](int ch) {
        const int s = ch & 1;
        const int k0 = ch << 6;
        if (tid < 128) {
            const int row = tid;
            const __nv_bfloat16 *srcH, *srcL;
            uint32_t sz = 16;
            if (CONV) {
                const int tap = k0 >> 12;
                const int coff = k0 & 4095;
                long sr = (long)m0 + row + tap - 1;
                const int tt = (row & 31) + tap - 1;
                if (tt < 0 || tt > 31) { sz = 0; sr = m0 + row; }
                srcH = Ahi + sr * ldA + coff;
                srcL = Alo + sr * ldA + coff;
            } else {
                srcH = Ahi + (size_t)(m0 + row) * ldA + k0;
                srcL = Alo + (size_t)(m0 + row) * ldA + k0;
            }
            const uint32_t d = sb + s * ST + row * 128;
            const int xm = row & 7;
#pragma unroll
            for (int c = 0; c < 8; c++) {
                const uint32_t cc = (uint32_t)((c ^ xm) << 4);
                cp16(d + cc, srcH + c * 8, sz);
                cp16(d + 16384 + cc, srcL + c * 8, sz);
            }
        } else {
            const int row = tid - 128;
            const __nv_bfloat16* srcH = Bhi + (size_t)(n0 + row) * ldB + k0;
            const __nv_bfloat16* srcL = Blo + (size_t)(n0 + row) * ldB + k0;
            const uint32_t d = sb + s * ST + 32768 + row * 128;
            const int xm = row & 7;
#pragma unroll
            for (int c = 0; c < 8; c++) {
                const uint32_t cc = (uint32_t)((c ^ xm) << 4);
                cp16(d + cc, srcH + c * 8, 16);
                cp16(d + 16384 + cc, srcL + c * 8, 16);
            }
        }
        asm volatile("cp.async.commit_group;" ::: "memory");
    };

    issue_load(0);
    for (int ch = 0; ch < NCH; ch++) {
        if (ch + 1 < NCH) issue_load(ch + 1);
        if (ch + 1 < NCH) asm volatile("cp.async.wait_group 1;" ::: "memory");
        else              asm volatile("cp.async.wait_group 0;" ::: "memory");
        __syncthreads();
        const uint32_t base = sb + (ch & 1) * ST;
        // 4 k16 steps
#pragma unroll
        for (int ks = 0; ks < 4; ks++) {
            const int kc = ks * 2 + ksel;
            uint32_t ah[4][4], al[4][4];
#pragma unroll
            for (int im = 0; im < 4; im++) {
                const int row = wm + im * 16 + rsel;
                const uint32_t a = base + row * 128 + (uint32_t)(((kc ^ (row & 7))) << 4);
                ldm4(ah[im], a);
                ldm4(al[im], a + 16384);
            }
            uint32_t bh[4][2], bl[4][2];
#pragma unroll
            for (int j2 = 0; j2 < 2; j2++) {
                const int row = wn + j2 * 16 + rsel;
                const uint32_t a = base + 32768 + row * 128 + (uint32_t)(((kc ^ (row & 7))) << 4);
                uint32_t t[4];
                ldm4(t, a);
                bh[j2 * 2][0] = t[0]; bh[j2 * 2][1] = t[2];
                bh[j2 * 2 + 1][0] = t[1]; bh[j2 * 2 + 1][1] = t[3];
                ldm4(t, a + 16384);
                bl[j2 * 2][0] = t[0]; bl[j2 * 2][1] = t[2];
                bl[j2 * 2 + 1][0] = t[1]; bl[j2 * 2 + 1][1] = t[3];
            }
#pragma unroll
            for (int im = 0; im < 4; im++)
#pragma unroll
                for (int jn = 0; jn < 4; jn++) {
                    mma16816(acc[im][jn], ah[im], bh[jn]);
                    mma16816(acc[im][jn], al[im], bh[jn]);
                    mma16816(acc[im][jn], ah[im], bl[jn]);
                }
        }
        __syncthreads();
    }

    // ---- epilogue ----
    const int g = lane >> 2, t4 = lane & 3;
#pragma unroll
    for (int im = 0; im < 4; im++) {
#pragma unroll
        for (int jn = 0; jn < 4; jn++) {
            const int n = n0 + wn + jn * 8 + t4 * 2;
            const float bv0 = bias[n], bv1 = bias[n + 1];
            float ew0 = 0.f, ew1 = 0.f;
            if (EPI == 2) { ew0 = exW[(size_t)n * 257]; ew1 = exW[(size_t)(n + 1) * 257]; }
#pragma unroll
            for (int h = 0; h < 2; h++) {
                const int m = m0 + wm + im * 16 + g + h * 8;
                float v0 = acc[im][jn][h * 2 + 0] + bv0;
                float v1 = acc[im][jn][h * 2 + 1] + bv1;
                if (EPI == 2) {
                    const float ec = exCol[m];
                    v0 += ec * ew0; v1 += ec * ew1;
                }
                if (EPI >= 2) { v0 = fmaxf(v0, 0.f); v1 = fmaxf(v1, 0.f); }
                const size_t off = (size_t)m * N + n;
                if (EPI != 2)
                    *reinterpret_cast<float2*>(Cf + off) = make_float2(v0, v1);
                if (EPI == 0 || EPI == 2) {
                    __nv_bfloat16 h0, l0, h1, l1;
                    splitbf(v0, h0, l0); splitbf(v1, h1, l1);
                    __nv_bfloat162 ph, pl;
                    ph.x = h0; ph.y = h1; pl.x = l0; pl.y = l1;
                    *reinterpret_cast<__nv_bfloat162*>(Chi + off) = ph;
                    *reinterpret_cast<__nv_bfloat162*>(Clo + off) = pl;
                }
            }
        }
    }
}

// ======================= gated attention combine =======================
__global__ void __launch_bounds__(256) gated_kernel(
    const float* __restrict__ pv, const float* __restrict__ pu,
    const float* __restrict__ gw, const float* __restrict__ gb,
    float* __restrict__ Amat)
{
    int m = blockIdx.x * 8 + (threadIdx.x >> 5);
    int lane = threadIdx.x & 31;
    float acc = 0.f;
#pragma unroll
    for (int i = 0; i < 8; i++) {
        int d = lane + i * 32;
        float v = tanhf(pv[(size_t)m * 256 + d]);
        float u = 1.f / (1.f + expf(-pu[(size_t)m * 256 + d]));
        acc += v * u * gw[d];
    }
#pragma unroll
    for (int o = 16; o; o >>= 1) acc += __shfl_xor_sync(0xffffffffu, acc, o);
    if (lane == 0) Amat[m] = acc + gb[0];
}

// ======================= softmax over T + bag + At =======================
__global__ void __launch_bounds__(256) softbag_kernel(
    const float* __restrict__ Amat, const float* __restrict__ feat,
    float* __restrict__ bag, float* __restrict__ outAt)
{
    __shared__ float p[32];
    int b = blockIdx.x;
    int tid = threadIdx.x;
    if (tid < 32) {
        float v = Amat[b * 32 + tid];
        outAt[b * 32 + tid] = v;
        float mx = v;
#pragma unroll
        for (int o = 16; o; o >>= 1) mx = fmaxf(mx, __shfl_xor_sync(0xffffffffu, mx, o));
        float e = expf(v - mx);
        float s = e;
#pragma unroll
        for (int o = 16; o; o >>= 1) s += __shfl_xor_sync(0xffffffffu, s, o);
        p[tid] = e / s;
    }
    __syncthreads();
    float acc = 0.f;
#pragma unroll 8
    for (int t = 0; t < 32; t++) acc += p[t] * feat[(size_t)(b * 32 + t) * 256 + tid];
    bag[b * 256 + tid] = acc;
}

// ======================= bag classifier =======================
__global__ void __launch_bounds__(256) bagclf_kernel(
    const float* __restrict__ bag,
    const float* __restrict__ w0, const float* __restrict__ b0,
    const float* __restrict__ w1, const float* __restrict__ b1,
    const float* __restrict__ w2, const float* __restrict__ b2,
    const float* __restrict__ w3, const float* __restrict__ b3,
    float* __restrict__ outp)
{
    __shared__ float sb[8 * 256];
    __shared__ float sh[8 * 256];
    int base = blockIdx.x * 8;
    int tid = threadIdx.x;
#pragma unroll
    for (int i = 0; i < 8; i++) sb[tid + i * 256] = bag[(size_t)base * 256 + tid + i * 256];
    __syncthreads();
    {
        float acc[8] = {0, 0, 0, 0, 0, 0, 0, 0};
        const float* w = w0 + (size_t)tid * 256;
        for (int l = 0; l < 256; l++) {
            float wv = w[l];
#pragma unroll
            for (int r = 0; r < 8; r++) acc[r] += wv * sb[r * 256 + l];
        }
        float bb = b0[tid];
#pragma unroll
        for (int r = 0; r < 8; r++) sh[r * 256 + tid] = fmaxf(acc[r] + bb, 0.f);
    }
    __syncthreads();
    if (tid < 128) {
        float acc[8] = {0, 0, 0, 0, 0, 0, 0, 0};
        const float* w = w1 + (size_t)tid * 256;
        for (int l = 0; l < 256; l++) {
            float wv = w[l];
#pragma unroll
            for (int r = 0; r < 8; r++) acc[r] += wv * sh[r * 256 + l];
        }
        float bb = b1[tid];
#pragma unroll
        for (int r = 0; r < 8; r++) sb[r * 128 + tid] = fmaxf(acc[r] + bb, 0.f);
    }
    __syncthreads();
    if (tid < 32) {
        float acc[8] = {0, 0, 0, 0, 0, 0, 0, 0};
        const float* w = w2 + (size_t)tid * 128;
        for (int l = 0; l < 128; l++) {
            float wv = w[l];
#pragma unroll
            for (int r = 0; r < 8; r++) acc[r] += wv * sb[r * 128 + l];
        }
        float bb = b2[tid];
#pragma unroll
        for (int r = 0; r < 8; r++) sh[r * 32 + tid] = fmaxf(acc[r] + bb, 0.f);
    }
    __syncthreads();
    if (tid < 8) {
        float a = 0.f;
        for (int j = 0; j < 32; j++) a += w3[j] * sh[tid * 32 + j];
        float o1 = 1.f / (1.f + expf(-(a + b3[0])));
        outp[(size_t)(base + tid) * 2 + 0] = 0.5f * o1;
    }
}

// ======================= seg tail =======================
__global__ void __launch_bounds__(256) segtail_kernel(
    const float* __restrict__ h1,
    const float* __restrict__ w2, const float* __restrict__ b2,
    const float* __restrict__ w3, const float* __restrict__ b3,
    float* __restrict__ out_seg)
{
    __shared__ float sw2[128 * 32];
    __shared__ float sh1[8 * 128];
    int m0 = blockIdx.x * 8;
    int tid = threadIdx.x;
#pragma unroll
    for (int i = 0; i < 16; i++) {
        int idx = tid + i * 256;
        sw2[(idx & 127) * 32 + (idx >> 7)] = w2[idx];
    }
#pragma unroll
    for (int i = 0; i < 4; i++) {
        int idx = tid + i * 256;
        sh1[idx] = h1[(size_t)m0 * 128 + idx];
    }
    __syncthreads();
    int r = tid >> 5, j = tid & 31;
    float acc = b2[j];
#pragma unroll 8
    for (int l = 0; l < 128; l++) acc += sw2[l * 32 + j] * sh1[r * 128 + l];
    float h2 = fmaxf(acc, 0.f);
    float v = h2 * w3[j];
#pragma unroll
    for (int o = 16; o; o >>= 1) v += __shfl_xor_sync(0xffffffffu, v, o);
    if (j == 0) out_seg[m0 + r] = 1.f / (1.f + expf(-(v + b3[0])));
}

// ======================= per-sample 2-means (cosine) =======================
__global__ void __launch_bounds__(256) kmeans_kernel(
    const float* __restrict__ feat, const float* __restrict__ seg,
    float* __restrict__ out_assign, float* __restrict__ out_pair)
{
    __shared__ float sf[32 * 256];
    __shared__ float sc[2 * 256];
    __shared__ float scn[2 * 256];
    __shared__ int sassign[32];
    __shared__ int s_ctrl[3];
    int b = blockIdx.x;
    int tid = threadIdx.x;
    int lane = tid & 31, w = tid >> 5;

#pragma unroll
    for (int i = 0; i < 32; i++) sf[tid + i * 256] = feat[(size_t)b * 8192 + tid + i * 256];
    sc[tid] = sf[tid];
    sc[256 + tid] = sf[4096 + tid];
    if (tid == 0) s_ctrl[2] = 0;
    __syncthreads();

    int final_mask = 0;
    for (int it = 0; it < 100; it++) {
        if (w < 2) {
            float s = 0.f;
#pragma unroll
            for (int i = 0; i < 8; i++) {
                float v = sc[w * 256 + lane + i * 32];
                s += v * v;
            }
#pragma unroll
            for (int o = 16; o; o >>= 1) s += __shfl_xor_sync(0xffffffffu, s, o);
            float inv = 1.f / (sqrtf(s) + 1e-8f);
#pragma unroll
            for (int i = 0; i < 8; i++)
                scn[w * 256 + lane + i * 32] = sc[w * 256 + lane + i * 32] * inv;
        }
        __syncthreads();
#pragma unroll
        for (int p = 0; p < 4; p++) {
            int t = w * 4 + p;
            float s0 = 0.f, s1 = 0.f;
#pragma unroll
            for (int i = 0; i < 8; i++) {
                float fv = sf[t * 256 + lane + i * 32];
                s0 += fv * scn[lane + i * 32];
                s1 += fv * scn[256 + lane + i * 32];
            }
#pragma unroll
            for (int o = 16; o; o >>= 1) {
                s0 += __shfl_xor_sync(0xffffffffu, s0, o);
                s1 += __shfl_xor_sync(0xffffffffu, s1, o);
            }
            if (lane == 0) sassign[t] = (s1 > s0) ? 1 : 0;
        }
        __syncthreads();
        if (tid == 0) {
            int mask = 0;
#pragma unroll
            for (int t = 0; t < 32; t++) mask |= sassign[t] << t;
            s_ctrl[0] = mask;
            s_ctrl[1] = (it > 0 && mask == s_ctrl[2]) ? 1 : 0;
            s_ctrl[2] = mask;
        }
        __syncthreads();
        int mask = s_ctrl[0];
        final_mask = mask;
        if (s_ctrl[1]) break;
        int cnt1 = __popc(mask);
        int cnt0 = 32 - cnt1;
        float a0 = 0.f, a1 = 0.f;
#pragma unroll
        for (int t = 0; t < 32; t++) {
            float fv = sf[t * 256 + tid];
            if ((mask >> t) & 1) a1 += fv; else a0 += fv;
        }
        if (cnt0 > 0) sc[tid] = a0 / (float)cnt0;
        if (cnt1 > 0) sc[256 + tid] = a1 / (float)cnt1;
        __syncthreads();
    }

    if (tid < 32) {
        int bit = (final_mask >> tid) & 1;
        out_assign[b * 32 + tid] = (float)bit;
        float s = seg[b * 32 + tid];
        float v0 = bit ? 0.f : s;
        float v1 = bit ? s : 0.f;
#pragma unroll
        for (int o = 16; o; o >>= 1) {
            v0 += __shfl_xor_sync(0xffffffffu, v0, o);
            v1 += __shfl_xor_sync(0xffffffffu, v1, o);
        }
        int cnt1 = __popc(final_mask);
        int cnt0 = 32 - cnt1;
        float m0 = (cnt0 > 0) ? v0 / (float)cnt0 : -INFINITY;
        float m1 = (cnt1 > 0) ? v1 / (float)cnt1 : -INFINITY;
        if (tid == 0) out_pair[(size_t)b * 2 + 1] = 0.5f * fmaxf(m0, m1);
    }
}

// ======================= launch =======================
extern "C" void kernel_launch(void* const* d_in, const int* in_sizes, int n_in,
                              void* d_out, int out_size)
{
    const float* x      = (const float*)d_in[0];
    const float* tsn_w  = (const float*)d_in[1];
    const float* tsn_b  = (const float*)d_in[2];
    const float* aV_w   = (const float*)d_in[3];
    const float* aV_b   = (const float*)d_in[4];
    const float* aU_w   = (const float*)d_in[5];
    const float* aU_b   = (const float*)d_in[6];
    const float* gate_w = (const float*)d_in[7];
    const float* gate_b = (const float*)d_in[8];
    const float* cb_w0 = (const float*)d_in[9],  *cb_b0 = (const float*)d_in[10];
    const float* cb_w1 = (const float*)d_in[11], *cb_b1 = (const float*)d_in[12];
    const float* cb_w2 = (const float*)d_in[13], *cb_b2 = (const float*)d_in[14];
    const float* cb_w3 = (const float*)d_in[15], *cb_b3 = (const float*)d_in[16];
    const float* cs_w0 = (const float*)d_in[17], *cs_b0 = (const float*)d_in[18];
    const float* cs_w1 = (const float*)d_in[19], *cs_b1 = (const float*)d_in[20];
    const float* cs_w2 = (const float*)d_in[21], *cs_b2 = (const float*)d_in[22];
    const float* cs_w3 = (const float*)d_in[23], *cs_b3 = (const float*)d_in[24];

    float* out = (float*)d_out;
    float* feat    = out + OFF_FEAT;
    float* oAssign = out + OFF_ASSIGN;
    float* oSeg    = out + OFF_SEG;
    float* oOut    = out + OFF_OUT;
    float* oAt     = out + OFF_AT;

    __nv_bfloat16 *xhi, *xlo, *wthi, *wtlo, *bwh, *bwl, *fhi, *flo, *h0hi, *h0lo;
    float *preV, *preU, *Amat, *bag, *h1;
    cudaGetSymbolAddress((void**)&xhi, g_xhi);   cudaGetSymbolAddress((void**)&xlo, g_xlo);
    cudaGetSymbolAddress((void**)&wthi, g_wthi); cudaGetSymbolAddress((void**)&wtlo, g_wtlo);
    cudaGetSymbolAddress((void**)&bwh, g_bwh);   cudaGetSymbolAddress((void**)&bwl, g_bwl);
    cudaGetSymbolAddress((void**)&fhi, g_fhi);   cudaGetSymbolAddress((void**)&flo, g_flo);
    cudaGetSymbolAddress((void**)&h0hi, g_h0hi); cudaGetSymbolAddress((void**)&h0lo, g_h0lo);
    cudaGetSymbolAddress((void**)&preV, g_preV); cudaGetSymbolAddress((void**)&preU, g_preU);
    cudaGetSymbolAddress((void**)&Amat, g_Amat); cudaGetSymbolAddress((void**)&bag, g_bag);
    cudaGetSymbolAddress((void**)&h1, g_h1);

    const int SMB = 2 * ST;   // 131072
    cudaFuncSetAttribute(mm_gemm<1, 0>, cudaFuncAttributeMaxDynamicSharedMemorySize, SMB);
    cudaFuncSetAttribute(mm_gemm<0, 1>, cudaFuncAttributeMaxDynamicSharedMemorySize, SMB);
    cudaFuncSetAttribute(mm_gemm<0, 2>, cudaFuncAttributeMaxDynamicSharedMemorySize, SMB);
    cudaFuncSetAttribute(mm_gemm<0, 3>, cudaFuncAttributeMaxDynamicSharedMemorySize, SMB);

    // 1) splits / repacks
    split_x_k<<<65536, 256>>>((const float4*)x, (__nv_bfloat162*)xhi, (__nv_bfloat162*)xlo);
    splitw_conv_k<<<(L_ * KCONV) / 256, 256>>>(tsn_w, wthi, wtlo);
    splitw_gen_k<<<256, 256>>>(aV_w, 256, 65536, bwh, bwl);
    splitw_gen_k<<<256, 256>>>(aU_w, 256, 65536, bwh + 65536, bwl + 65536);
    splitw_gen_k<<<256, 256>>>(cs_w0, 257, 65536, bwh + 131072, bwl + 131072);
    splitw_gen_k<<<128, 256>>>(cs_w1, 256, 32768, bwh + 196608, bwl + 196608);

    // 2) conv-as-GEMM -> feature fp32 + fhi/flo
    mm_gemm<1, 0><<<dim3(2, 128), 256, SMB>>>(xhi, xlo, FIN, wthi, wtlo, KCONV,
                                              tsn_b, nullptr, nullptr,
                                              feat, fhi, flo, 256, KCONV);
    // 3) attention projections
    mm_gemm<0, 1><<<dim3(2, 128), 256, SMB>>>(fhi, flo, 256, bwh, bwl, 256,
                                              aV_b, nullptr, nullptr,
                                              preV, nullptr, nullptr, 256, 256);
    mm_gemm<0, 1><<<dim3(2, 128), 256, SMB>>>(fhi, flo, 256, bwh + 65536, bwl + 65536, 256,
                                              aU_b, nullptr, nullptr,
                                              preU, nullptr, nullptr, 256, 256);
    // 4) gated combine + softmax/bag + bag classifier
    gated_kernel<<<M_ / 8, 256>>>(preV, preU, gate_w, gate_b, Amat);
    softbag_kernel<<<B_, 256>>>(Amat, feat, bag, oAt);
    bagclf_kernel<<<B_ / 8, 256>>>(bag, cb_w0, cb_b0, cb_w1, cb_b1,
                                   cb_w2, cb_b2, cb_w3, cb_b3, oOut);
    // 5) seg classifier
    mm_gemm<0, 2><<<dim3(2, 128), 256, SMB>>>(fhi, flo, 256, bwh + 131072, bwl + 131072, 256,
                                              cs_b0, Amat, cs_w0 + 256,
                                              nullptr, h0hi, h0lo, 256, 256);
    mm_gemm<0, 3><<<dim3(1, 128), 256, SMB>>>(h0hi, h0lo, 256, bwh + 196608, bwl + 196608, 256,
                                              cs_b1, nullptr, nullptr,
                                              h1, nullptr, nullptr, 128, 256);
    segtail_kernel<<<M_ / 8, 256>>>(h1, cs_w2, cs_b2, cs_w3, cs_b3, oSeg);
    // 6) 2-means -> assigns + output[:,1]
    kmeans_kernel<<<B_, 256>>>(feat, oSeg, oAssign, oOut);
}

// round 5
// speedup vs baseline: 2.0829x; 1.3868x over previous
#include <cuda_runtime.h>
#include <cuda_fp16.h>
#include <math.h>
#include <stdint.h>

#define B_   512
#define T_   32
#define FIN  4096
#define L_   256
#define M_   (B_*T_)
#define KCONV (3*FIN)

#define OFF_FEAT   0
#define OFF_ASSIGN 4194304
#define OFF_SEG    4210688
#define OFF_OUT    4227072
#define OFF_AT     4228096

// -------- scratch (device globals) --------
__device__ __align__(16) __half g_xhi[(size_t)M_ * FIN];
__device__ __align__(16) __half g_xlo[(size_t)M_ * FIN];
__device__ __align__(16) __half g_wt[(size_t)L_ * KCONV];    // conv weight fp16 [n][k]
__device__ __align__(16) __half g_bw[229376];                // aV|aU|cs0|cs1 fp16 [n][256]
__device__ __align__(16) __half g_fhi[(size_t)M_ * L_];
__device__ __align__(16) __half g_flo[(size_t)M_ * L_];
__device__ __align__(16) __half g_h0hi[(size_t)M_ * 256];
__device__ __align__(16) __half g_h0lo[(size_t)M_ * 256];
__device__ float g_preV[(size_t)M_ * 256];
__device__ float g_preU[(size_t)M_ * 256];
__device__ float g_Amat[M_];
__device__ float g_bag[B_ * L_];
__device__ float g_h1[(size_t)M_ * 128];

// ======================= helpers =======================
__device__ __forceinline__ void splith(float v, __half& h, __half& l) {
    h = __float2half(v);
    l = __float2half(v - __half2float(h));
}
__device__ __forceinline__ uint32_t smem_u32(const void* p) {
    uint32_t a;
    asm("{ .reg .u64 t; cvta.to.shared.u64 t, %1; cvt.u32.u64 %0, t; }" : "=r"(a) : "l"(p));
    return a;
}
__device__ __forceinline__ void cp16(uint32_t dst, const void* src, uint32_t sz) {
    asm volatile("cp.async.cg.shared.global [%0], [%1], 16, %2;"
                 :: "r"(dst), "l"(src), "r"(sz) : "memory");
}
__device__ __forceinline__ void ldm4(uint32_t* r, uint32_t addr) {
    asm volatile("ldmatrix.sync.aligned.m8n8.x4.shared.b16 {%0,%1,%2,%3}, [%4];"
                 : "=r"(r[0]), "=r"(r[1]), "=r"(r[2]), "=r"(r[3]) : "r"(addr));
}
__device__ __forceinline__ void mma16816(float* c, const uint32_t* a, const uint32_t* b) {
    asm volatile("mma.sync.aligned.m16n8k16.row.col.f32.f16.f16.f32 "
                 "{%0,%1,%2,%3}, {%4,%5,%6,%7}, {%8,%9}, {%0,%1,%2,%3};"
                 : "+f"(c[0]), "+f"(c[1]), "+f"(c[2]), "+f"(c[3])
                 : "r"(a[0]), "r"(a[1]), "r"(a[2]), "r"(a[3]), "r"(b[0]), "r"(b[1]));
}

// ======================= split / repack kernels =======================
__global__ void split_x_k(const float4* __restrict__ x,
                          __half2* __restrict__ hi, __half2* __restrict__ lo) {
    size_t i = (size_t)blockIdx.x * 256 + threadIdx.x;
    float4 v = x[i];
    __half h[4], l[4];
    splith(v.x, h[0], l[0]); splith(v.y, h[1], l[1]);
    splith(v.z, h[2], l[2]); splith(v.w, h[3], l[3]);
    __half2 a, b, c, d;
    a.x = h[0]; a.y = h[1]; b.x = h[2]; b.y = h[3];
    c.x = l[0]; c.y = l[1]; d.x = l[2]; d.y = l[3];
    hi[2 * i] = a; hi[2 * i + 1] = b;
    lo[2 * i] = c; lo[2 * i + 1] = d;
}

__global__ void splitw_conv_k(const float* __restrict__ w, __half* __restrict__ o) {
    int idx = blockIdx.x * 256 + threadIdx.x;          // [n][k], k = tap*4096 + c
    int n = idx / KCONV;
    int k = idx - n * KCONV;
    int tap = k >> 12, c = k & 4095;
    o[idx] = __float2half(w[(size_t)n * KCONV + c * 3 + tap]);
}

__global__ void splitw_gen_k(const float* __restrict__ w, int srcStride, int total,
                             __half* __restrict__ o) {
    int idx = blockIdx.x * 256 + threadIdx.x;
    if (idx >= total) return;
    int n = idx >> 8, k = idx & 255;
    o[idx] = __float2half(w[(size_t)n * srcStride + k]);
}

// ======================= HMMA GEMM (mma.sync fp16, 2-pass A hi/lo) =======================
// D[m][n] = epi( sum_k A[m][k]*B[n][k] + bias[n] ),  A split hi/lo fp16, B single fp16.
// CTA tile 128x128, BK=64, 256 threads (8 warps, warp tile 64x32), cp.async 2-stage.
// EPI: 0=bias, write fp32 + fp16 hi/lo  (conv -> feature)
//      1=bias, write fp32               (preV / preU)
//      2=relu(bias + exCol[m]*exW[n*257]), write fp16 hi/lo  (seg layer0)
//      3=relu(bias), write fp32         (seg layer1)
#define ST 49152
template<int CONV, int EPI>
__global__ void __launch_bounds__(256, 2) mm_gemm(
    const __half* __restrict__ Ahi, const __half* __restrict__ Alo, int ldA,
    const __half* __restrict__ Bw, int ldB,
    const float* __restrict__ bias, const float* __restrict__ exCol,
    const float* __restrict__ exW,
    float* __restrict__ Cf, __half* __restrict__ Chi, __half* __restrict__ Clo,
    int N, int K)
{
    extern __shared__ __align__(128) char smem[];
    const int tid = threadIdx.x;
    const int m0 = blockIdx.y * 128;
    const int n0 = blockIdx.x * 128;
    const uint32_t sb = smem_u32(smem);
    const int NCH = K >> 6;

    const int lane = tid & 31, warp = tid >> 5;
    const int wm = (warp >> 2) * 64, wn = (warp & 3) * 32;
    const int rsel = lane & 15, ksel = lane >> 4;

    float acc[4][4][4];
#pragma unroll
    for (int i = 0; i < 4; i++)
#pragma unroll
        for (int j = 0; j < 4; j++)
#pragma unroll
            for (int u = 0; u < 4; u++) acc[i][j][u] = 0.f;

    auto issue_load = [&](int ch) {
        const int s = ch & 1;
        const int k0 = ch << 6;
        if (tid < 128) {
            const int row = tid;
            const __half *srcH, *srcL;
            uint32_t sz = 16;
            if (CONV) {
                const int tap = k0 >> 12;
                const int coff = k0 & 4095;
                long sr = (long)m0 + row + tap - 1;
                const int tt = (row & 31) + tap - 1;
                if (tt < 0 || tt > 31) { sz = 0; sr = m0 + row; }
                srcH = Ahi + sr * ldA + coff;
                srcL = Alo + sr * ldA + coff;
            } else {
                srcH = Ahi + (size_t)(m0 + row) * ldA + k0;
                srcL = Alo + (size_t)(m0 + row) * ldA + k0;
            }
            const uint32_t d = sb + s * ST + row * 128;
            const int xm = row & 7;
#pragma unroll
            for (int c = 0; c < 8; c++) {
                const uint32_t cc = (uint32_t)((c ^ xm) << 4);
                cp16(d + cc, srcH + c * 8, sz);
                cp16(d + 16384 + cc, srcL + c * 8, sz);
            }
        } else {
            const int row = tid - 128;
            const __half* srcB = Bw + (size_t)(n0 + row) * ldB + k0;
            const uint32_t d = sb + s * ST + 32768 + row * 128;
            const int xm = row & 7;
#pragma unroll
            for (int c = 0; c < 8; c++) {
                const uint32_t cc = (uint32_t)((c ^ xm) << 4);
                cp16(d + cc, srcB + c * 8, 16);
            }
        }
        asm volatile("cp.async.commit_group;" ::: "memory");
    };

    issue_load(0);
    for (int ch = 0; ch < NCH; ch++) {
        if (ch + 1 < NCH) issue_load(ch + 1);
        if (ch + 1 < NCH) asm volatile("cp.async.wait_group 1;" ::: "memory");
        else              asm volatile("cp.async.wait_group 0;" ::: "memory");
        __syncthreads();
        const uint32_t base = sb + (ch & 1) * ST;
#pragma unroll
        for (int ks = 0; ks < 4; ks++) {
            const int kc = ks * 2 + ksel;
            uint32_t ah[4][4], al[4][4];
#pragma unroll
            for (int im = 0; im < 4; im++) {
                const int row = wm + im * 16 + rsel;
                const uint32_t a = base + row * 128 + (uint32_t)(((kc ^ (row & 7))) << 4);
                ldm4(ah[im], a);
                ldm4(al[im], a + 16384);
            }
            uint32_t bh[4][2];
#pragma unroll
            for (int j2 = 0; j2 < 2; j2++) {
                const int row = wn + j2 * 16 + rsel;
                const uint32_t a = base + 32768 + row * 128 + (uint32_t)(((kc ^ (row & 7))) << 4);
                uint32_t t[4];
                ldm4(t, a);
                bh[j2 * 2][0] = t[0]; bh[j2 * 2][1] = t[2];
                bh[j2 * 2 + 1][0] = t[1]; bh[j2 * 2 + 1][1] = t[3];
            }
#pragma unroll
            for (int im = 0; im < 4; im++)
#pragma unroll
                for (int jn = 0; jn < 4; jn++) {
                    mma16816(acc[im][jn], ah[im], bh[jn]);
                    mma16816(acc[im][jn], al[im], bh[jn]);
                }
        }
        __syncthreads();
    }

    // ---- epilogue ----
    const int g = lane >> 2, t4 = lane & 3;
#pragma unroll
    for (int im = 0; im < 4; im++) {
#pragma unroll
        for (int jn = 0; jn < 4; jn++) {
            const int n = n0 + wn + jn * 8 + t4 * 2;
            const float bv0 = bias[n], bv1 = bias[n + 1];
            float ew0 = 0.f, ew1 = 0.f;
            if (EPI == 2) { ew0 = exW[(size_t)n * 257]; ew1 = exW[(size_t)(n + 1) * 257]; }
#pragma unroll
            for (int h = 0; h < 2; h++) {
                const int m = m0 + wm + im * 16 + g + h * 8;
                float v0 = acc[im][jn][h * 2 + 0] + bv0;
                float v1 = acc[im][jn][h * 2 + 1] + bv1;
                if (EPI == 2) {
                    const float ec = exCol[m];
                    v0 += ec * ew0; v1 += ec * ew1;
                }
                if (EPI >= 2) { v0 = fmaxf(v0, 0.f); v1 = fmaxf(v1, 0.f); }
                const size_t off = (size_t)m * N + n;
                if (EPI != 2)
                    *reinterpret_cast<float2*>(Cf + off) = make_float2(v0, v1);
                if (EPI == 0 || EPI == 2) {
                    __half h0, l0, h1, l1;
                    splith(v0, h0, l0); splith(v1, h1, l1);
                    __half2 ph, pl;
                    ph.x = h0; ph.y = h1; pl.x = l0; pl.y = l1;
                    *reinterpret_cast<__half2*>(Chi + off) = ph;
                    *reinterpret_cast<__half2*>(Clo + off) = pl;
                }
            }
        }
    }
}

// ======================= gated attention combine =======================
__global__ void __launch_bounds__(256) gated_kernel(
    const float* __restrict__ pv, const float* __restrict__ pu,
    const float* __restrict__ gw, const float* __restrict__ gb,
    float* __restrict__ Amat)
{
    int m = blockIdx.x * 8 + (threadIdx.x >> 5);
    int lane = threadIdx.x & 31;
    float acc = 0.f;
#pragma unroll
    for (int i = 0; i < 8; i++) {
        int d = lane + i * 32;
        float v = tanhf(pv[(size_t)m * 256 + d]);
        float u = 1.f / (1.f + expf(-pu[(size_t)m * 256 + d]));
        acc += v * u * gw[d];
    }
#pragma unroll
    for (int o = 16; o; o >>= 1) acc += __shfl_xor_sync(0xffffffffu, acc, o);
    if (lane == 0) Amat[m] = acc + gb[0];
}

// ======================= softmax over T + bag + At =======================
__global__ void __launch_bounds__(256) softbag_kernel(
    const float* __restrict__ Amat, const float* __restrict__ feat,
    float* __restrict__ bag, float* __restrict__ outAt)
{
    __shared__ float p[32];
    int b = blockIdx.x;
    int tid = threadIdx.x;
    if (tid < 32) {
        float v = Amat[b * 32 + tid];
        outAt[b * 32 + tid] = v;
        float mx = v;
#pragma unroll
        for (int o = 16; o; o >>= 1) mx = fmaxf(mx, __shfl_xor_sync(0xffffffffu, mx, o));
        float e = expf(v - mx);
        float s = e;
#pragma unroll
        for (int o = 16; o; o >>= 1) s += __shfl_xor_sync(0xffffffffu, s, o);
        p[tid] = e / s;
    }
    __syncthreads();
    float acc = 0.f;
#pragma unroll 8
    for (int t = 0; t < 32; t++) acc += p[t] * feat[(size_t)(b * 32 + t) * 256 + tid];
    bag[b * 256 + tid] = acc;
}

// ======================= bag classifier =======================
__global__ void __launch_bounds__(256) bagclf_kernel(
    const float* __restrict__ bag,
    const float* __restrict__ w0, const float* __restrict__ b0,
    const float* __restrict__ w1, const float* __restrict__ b1,
    const float* __restrict__ w2, const float* __restrict__ b2,
    const float* __restrict__ w3, const float* __restrict__ b3,
    float* __restrict__ outp)
{
    __shared__ float sb[8 * 256];
    __shared__ float sh[8 * 256];
    int base = blockIdx.x * 8;
    int tid = threadIdx.x;
#pragma unroll
    for (int i = 0; i < 8; i++) sb[tid + i * 256] = bag[(size_t)base * 256 + tid + i * 256];
    __syncthreads();
    {
        float acc[8] = {0, 0, 0, 0, 0, 0, 0, 0};
        const float* w = w0 + (size_t)tid * 256;
        for (int l = 0; l < 256; l++) {
            float wv = w[l];
#pragma unroll
            for (int r = 0; r < 8; r++) acc[r] += wv * sb[r * 256 + l];
        }
        float bb = b0[tid];
#pragma unroll
        for (int r = 0; r < 8; r++) sh[r * 256 + tid] = fmaxf(acc[r] + bb, 0.f);
    }
    __syncthreads();
    if (tid < 128) {
        float acc[8] = {0, 0, 0, 0, 0, 0, 0, 0};
        const float* w = w1 + (size_t)tid * 256;
        for (int l = 0; l < 256; l++) {
            float wv = w[l];
#pragma unroll
            for (int r = 0; r < 8; r++) acc[r] += wv * sh[r * 256 + l];
        }
        float bb = b1[tid];
#pragma unroll
        for (int r = 0; r < 8; r++) sb[r * 128 + tid] = fmaxf(acc[r] + bb, 0.f);
    }
    __syncthreads();
    if (tid < 32) {
        float acc[8] = {0, 0, 0, 0, 0, 0, 0, 0};
        const float* w = w2 + (size_t)tid * 128;
        for (int l = 0; l < 128; l++) {
            float wv = w[l];
#pragma unroll
            for (int r = 0; r < 8; r++) acc[r] += wv * sb[r * 128 + l];
        }
        float bb = b2[tid];
#pragma unroll
        for (int r = 0; r < 8; r++) sh[r * 32 + tid] = fmaxf(acc[r] + bb, 0.f);
    }
    __syncthreads();
    if (tid < 8) {
        float a = 0.f;
        for (int j = 0; j < 32; j++) a += w3[j] * sh[tid * 32 + j];
        float o1 = 1.f / (1.f + expf(-(a + b3[0])));
        outp[(size_t)(base + tid) * 2 + 0] = 0.5f * o1;
    }
}

// ======================= seg tail =======================
__global__ void __launch_bounds__(256) segtail_kernel(
    const float* __restrict__ h1,
    const float* __restrict__ w2, const float* __restrict__ b2,
    const float* __restrict__ w3, const float* __restrict__ b3,
    float* __restrict__ out_seg)
{
    __shared__ float sw2[128 * 32];
    __shared__ float sh1[8 * 128];
    int m0 = blockIdx.x * 8;
    int tid = threadIdx.x;
#pragma unroll
    for (int i = 0; i < 16; i++) {
        int idx = tid + i * 256;
        sw2[(idx & 127) * 32 + (idx >> 7)] = w2[idx];
    }
#pragma unroll
    for (int i = 0; i < 4; i++) {
        int idx = tid + i * 256;
        sh1[idx] = h1[(size_t)m0 * 128 + idx];
    }
    __syncthreads();
    int r = tid >> 5, j = tid & 31;
    float acc = b2[j];
#pragma unroll 8
    for (int l = 0; l < 128; l++) acc += sw2[l * 32 + j] * sh1[r * 128 + l];
    float h2 = fmaxf(acc, 0.f);
    float v = h2 * w3[j];
#pragma unroll
    for (int o = 16; o; o >>= 1) v += __shfl_xor_sync(0xffffffffu, v, o);
    if (j == 0) out_seg[m0 + r] = 1.f / (1.f + expf(-(v + b3[0])));
}

// ======================= per-sample 2-means (cosine) =======================
__global__ void __launch_bounds__(256) kmeans_kernel(
    const float* __restrict__ feat, const float* __restrict__ seg,
    float* __restrict__ out_assign, float* __restrict__ out_pair)
{
    __shared__ float sf[32 * 256];
    __shared__ float sc[2 * 256];
    __shared__ float scn[2 * 256];
    __shared__ int sassign[32];
    __shared__ int s_ctrl[3];
    int b = blockIdx.x;
    int tid = threadIdx.x;
    int lane = tid & 31, w = tid >> 5;

#pragma unroll
    for (int i = 0; i < 32; i++) sf[tid + i * 256] = feat[(size_t)b * 8192 + tid + i * 256];
    sc[tid] = sf[tid];
    sc[256 + tid] = sf[4096 + tid];
    if (tid == 0) s_ctrl[2] = 0;
    __syncthreads();

    int final_mask = 0;
    for (int it = 0; it < 100; it++) {
        if (w < 2) {
            float s = 0.f;
#pragma unroll
            for (int i = 0; i < 8; i++) {
                float v = sc[w * 256 + lane + i * 32];
                s += v * v;
            }
#pragma unroll
            for (int o = 16; o; o >>= 1) s += __shfl_xor_sync(0xffffffffu, s, o);
            float inv = 1.f / (sqrtf(s) + 1e-8f);
#pragma unroll
            for (int i = 0; i < 8; i++)
                scn[w * 256 + lane + i * 32] = sc[w * 256 + lane + i * 32] * inv;
        }
        __syncthreads();
#pragma unroll
        for (int p = 0; p < 4; p++) {
            int t = w * 4 + p;
            float s0 = 0.f, s1 = 0.f;
#pragma unroll
            for (int i = 0; i < 8; i++) {
                float fv = sf[t * 256 + lane + i * 32];
                s0 += fv * scn[lane + i * 32];
                s1 += fv * scn[256 + lane + i * 32];
            }
#pragma unroll
            for (int o = 16; o; o >>= 1) {
                s0 += __shfl_xor_sync(0xffffffffu, s0, o);
                s1 += __shfl_xor_sync(0xffffffffu, s1, o);
            }
            if (lane == 0) sassign[t] = (s1 > s0) ? 1 : 0;
        }
        __syncthreads();
        if (tid == 0) {
            int mask = 0;
#pragma unroll
            for (int t = 0; t < 32; t++) mask |= sassign[t] << t;
            s_ctrl[0] = mask;
            s_ctrl[1] = (it > 0 && mask == s_ctrl[2]) ? 1 : 0;
            s_ctrl[2] = mask;
        }
        __syncthreads();
        int mask = s_ctrl[0];
        final_mask = mask;
        if (s_ctrl[1]) break;
        int cnt1 = __popc(mask);
        int cnt0 = 32 - cnt1;
        float a0 = 0.f, a1 = 0.f;
#pragma unroll
        for (int t = 0; t < 32; t++) {
            float fv = sf[t * 256 + tid];
            if ((mask >> t) & 1) a1 += fv; else a0 += fv;
        }
        if (cnt0 > 0) sc[tid] = a0 / (float)cnt0;
        if (cnt1 > 0) sc[256 + tid] = a1 / (float)cnt1;
        __syncthreads();
    }

    if (tid < 32) {
        int bit = (final_mask >> tid) & 1;
        out_assign[b * 32 + tid] = (float)bit;
        float s = seg[b * 32 + tid];
        float v0 = bit ? 0.f : s;
        float v1 = bit ? s : 0.f;
#pragma unroll
        for (int o = 16; o; o >>= 1) {
            v0 += __shfl_xor_sync(0xffffffffu, v0, o);
            v1 += __shfl_xor_sync(0xffffffffu, v1, o);
        }
        int cnt1 = __popc(final_mask);
        int cnt0 = 32 - cnt1;
        float m0 = (cnt0 > 0) ? v0 / (float)cnt0 : -INFINITY;
        float m1 = (cnt1 > 0) ? v1 / (float)cnt1 : -INFINITY;
        if (tid == 0) out_pair[(size_t)b * 2 + 1] = 0.5f * fmaxf(m0, m1);
    }
}

// ======================= launch =======================
extern "C" void kernel_launch(void* const* d_in, const int* in_sizes, int n_in,
                              void* d_out, int out_size)
{
    const float* x      = (const float*)d_in[0];
    const float* tsn_w  = (const float*)d_in[1];
    const float* tsn_b  = (const float*)d_in[2];
    const float* aV_w   = (const float*)d_in[3];
    const float* aV_b   = (const float*)d_in[4];
    const float* aU_w   = (const float*)d_in[5];
    const float* aU_b   = (const float*)d_in[6];
    const float* gate_w = (const float*)d_in[7];
    const float* gate_b = (const float*)d_in[8];
    const float* cb_w0 = (const float*)d_in[9],  *cb_b0 = (const float*)d_in[10];
    const float* cb_w1 = (const float*)d_in[11], *cb_b1 = (const float*)d_in[12];
    const float* cb_w2 = (const float*)d_in[13], *cb_b2 = (const float*)d_in[14];
    const float* cb_w3 = (const float*)d_in[15], *cb_b3 = (const float*)d_in[16];
    const float* cs_w0 = (const float*)d_in[17], *cs_b0 = (const float*)d_in[18];
    const float* cs_w1 = (const float*)d_in[19], *cs_b1 = (const float*)d_in[20];
    const float* cs_w2 = (const float*)d_in[21], *cs_b2 = (const float*)d_in[22];
    const float* cs_w3 = (const float*)d_in[23], *cs_b3 = (const float*)d_in[24];

    float* out = (float*)d_out;
    float* feat    = out + OFF_FEAT;
    float* oAssign = out + OFF_ASSIGN;
    float* oSeg    = out + OFF_SEG;
    float* oOut    = out + OFF_OUT;
    float* oAt     = out + OFF_AT;

    __half *xhi, *xlo, *wt, *bw, *fhi, *flo, *h0hi, *h0lo;
    float *preV, *preU, *Amat, *bag, *h1;
    cudaGetSymbolAddress((void**)&xhi, g_xhi);   cudaGetSymbolAddress((void**)&xlo, g_xlo);
    cudaGetSymbolAddress((void**)&wt, g_wt);     cudaGetSymbolAddress((void**)&bw, g_bw);
    cudaGetSymbolAddress((void**)&fhi, g_fhi);   cudaGetSymbolAddress((void**)&flo, g_flo);
    cudaGetSymbolAddress((void**)&h0hi, g_h0hi); cudaGetSymbolAddress((void**)&h0lo, g_h0lo);
    cudaGetSymbolAddress((void**)&preV, g_preV); cudaGetSymbolAddress((void**)&preU, g_preU);
    cudaGetSymbolAddress((void**)&Amat, g_Amat); cudaGetSymbolAddress((void**)&bag, g_bag);
    cudaGetSymbolAddress((void**)&h1, g_h1);

    const int SMB = 2 * ST;   // 98304
    cudaFuncSetAttribute(mm_gemm<1, 0>, cudaFuncAttributeMaxDynamicSharedMemorySize, SMB);
    cudaFuncSetAttribute(mm_gemm<0, 1>, cudaFuncAttributeMaxDynamicSharedMemorySize, SMB);
    cudaFuncSetAttribute(mm_gemm<0, 2>, cudaFuncAttributeMaxDynamicSharedMemorySize, SMB);
    cudaFuncSetAttribute(mm_gemm<0, 3>, cudaFuncAttributeMaxDynamicSharedMemorySize, SMB);

    // launches 1-5 (ncu -s 5 skips these; #6 = conv GEMM gets profiled)
    split_x_k<<<65536, 256>>>((const float4*)x, (__half2*)xhi, (__half2*)xlo);
    splitw_conv_k<<<(L_ * KCONV) / 256, 256>>>(tsn_w, wt);
    splitw_gen_k<<<256, 256>>>(aV_w, 256, 65536, bw);
    splitw_gen_k<<<256, 256>>>(aU_w, 256, 65536, bw + 65536);
    splitw_gen_k<<<256, 256>>>(cs_w0, 257, 65536, bw + 131072);

    // #6: conv-as-GEMM -> feature fp32 + fhi/flo
    mm_gemm<1, 0><<<dim3(2, 128), 256, SMB>>>(xhi, xlo, FIN, wt, KCONV,
                                              tsn_b, nullptr, nullptr,
                                              feat, fhi, flo, 256, KCONV);

    splitw_gen_k<<<128, 256>>>(cs_w1, 256, 32768, bw + 196608);

    // attention projections
    mm_gemm<0, 1><<<dim3(2, 128), 256, SMB>>>(fhi, flo, 256, bw, 256,
                                              aV_b, nullptr, nullptr,
                                              preV, nullptr, nullptr, 256, 256);
    mm_gemm<0, 1><<<dim3(2, 128), 256, SMB>>>(fhi, flo, 256, bw + 65536, 256,
                                              aU_b, nullptr, nullptr,
                                              preU, nullptr, nullptr, 256, 256);
    // gated combine + softmax/bag + bag classifier
    gated_kernel<<<M_ / 8, 256>>>(preV, preU, gate_w, gate_b, Amat);
    softbag_kernel<<<B_, 256>>>(Amat, feat, bag, oAt);
    bagclf_kernel<<<B_ / 8, 256>>>(bag, cb_w0, cb_b0, cb_w1, cb_b1,
                                   cb_w2, cb_b2, cb_w3, cb_b3, oOut);
    // seg classifier
    mm_gemm<0, 2><<<dim3(2, 128), 256, SMB>>>(fhi, flo, 256, bw + 131072, 256,
                                              cs_b0, Amat, cs_w0 + 256,
                                              nullptr, h0hi, h0lo, 256, 256);
    mm_gemm<0, 3><<<dim3(1, 128), 256, SMB>>>(h0hi, h0lo, 256, bw + 196608, 256,
                                              cs_b1, nullptr, nullptr,
                                              h1, nullptr, nullptr, 128, 256);
    segtail_kernel<<<M_ / 8, 256>>>(h1, cs_w2, cs_b2, cs_w3, cs_b3, oSeg);
    // 2-means -> assigns + output[:,1]
    kmeans_kernel<<<B_, 256>>>(feat, oSeg, oAssign, oOut);
}

// round 6
// speedup vs baseline: 3.1050x; 1.4908x over previous
#include <cuda_runtime.h>
#include <cuda_fp16.h>
#include <math.h>
#include <stdint.h>

#define B_   512
#define T_   32
#define FIN  4096
#define L_   256
#define M_   (B_*T_)
#define KCONV (3*FIN)

#define OFF_FEAT   0
#define OFF_ASSIGN 4194304
#define OFF_SEG    4210688
#define OFF_OUT    4227072
#define OFF_AT     4228096

// -------- scratch (device globals) --------
__device__ __align__(16) __half g_xh[(size_t)M_ * FIN];      // x fp16 (single)
__device__ __align__(16) __half g_wt[(size_t)L_ * KCONV];    // conv weight fp16 [n][k]
__device__ __align__(16) __half g_bw[229376];                // aV|aU|cs0|cs1 fp16 [n][256]
__device__ __align__(16) __half g_fhi[(size_t)M_ * L_];
__device__ __align__(16) __half g_flo[(size_t)M_ * L_];
__device__ __align__(16) __half g_h0hi[(size_t)M_ * 256];
__device__ __align__(16) __half g_h0lo[(size_t)M_ * 256];
__device__ float g_preV[(size_t)M_ * 256];
__device__ float g_preU[(size_t)M_ * 256];
__device__ float g_Amat[M_];
__device__ float g_bag[B_ * L_];
__device__ float g_h1[(size_t)M_ * 128];

// ======================= helpers =======================
__device__ __forceinline__ void splith(float v, __half& h, __half& l) {
    h = __float2half(v);
    l = __float2half(v - __half2float(h));
}
__device__ __forceinline__ uint32_t smem_u32(const void* p) {
    uint32_t a;
    asm("{ .reg .u64 t; cvta.to.shared.u64 t, %1; cvt.u32.u64 %0, t; }" : "=r"(a) : "l"(p));
    return a;
}
__device__ __forceinline__ void cp16(uint32_t dst, const void* src, uint32_t sz) {
    asm volatile("cp.async.cg.shared.global [%0], [%1], 16, %2;"
                 :: "r"(dst), "l"(src), "r"(sz) : "memory");
}
__device__ __forceinline__ void ldm4(uint32_t* r, uint32_t addr) {
    asm volatile("ldmatrix.sync.aligned.m8n8.x4.shared.b16 {%0,%1,%2,%3}, [%4];"
                 : "=r"(r[0]), "=r"(r[1]), "=r"(r[2]), "=r"(r[3]) : "r"(addr));
}
__device__ __forceinline__ void mma16816(float* c, const uint32_t* a, const uint32_t* b) {
    asm volatile("mma.sync.aligned.m16n8k16.row.col.f32.f16.f16.f32 "
                 "{%0,%1,%2,%3}, {%4,%5,%6,%7}, {%8,%9}, {%0,%1,%2,%3};"
                 : "+f"(c[0]), "+f"(c[1]), "+f"(c[2]), "+f"(c[3])
                 : "r"(a[0]), "r"(a[1]), "r"(a[2]), "r"(a[3]), "r"(b[0]), "r"(b[1]));
}

// ======================= convert / repack kernels =======================
__global__ void conv_x_k(const float4* __restrict__ x, __half2* __restrict__ o) {
    size_t i = (size_t)blockIdx.x * 256 + threadIdx.x;
    float4 v = x[i];
    __half2 a, b;
    a.x = __float2half(v.x); a.y = __float2half(v.y);
    b.x = __float2half(v.z); b.y = __float2half(v.w);
    o[2 * i] = a; o[2 * i + 1] = b;
}

__global__ void splitw_conv_k(const float* __restrict__ w, __half* __restrict__ o) {
    int idx = blockIdx.x * 256 + threadIdx.x;          // [n][k], k = tap*4096 + c
    int n = idx / KCONV;
    int k = idx - n * KCONV;
    int tap = k >> 12, c = k & 4095;
    o[idx] = __float2half(w[(size_t)n * KCONV + c * 3 + tap]);
}

__global__ void splitw_gen_k(const float* __restrict__ w, int srcStride, int total,
                             __half* __restrict__ o) {
    int idx = blockIdx.x * 256 + threadIdx.x;
    if (idx >= total) return;
    int n = idx >> 8, k = idx & 255;
    o[idx] = __float2half(w[(size_t)n * srcStride + k]);
}

// ======================= HMMA GEMM (mma.sync fp16) =======================
// D[m][n] = epi( sum_k A[m][k]*B[n][k] + bias[n] )
// TP=1: A given as hi/lo fp16 pair, 2 MMA passes.  TP=0: A single fp16, 1 pass.
// CTA tile 128x128, BK=64, 256 threads (8 warps, warp tile 64x32), cp.async 2-stage.
// EPI: 0=bias, write fp32 + fp16 hi/lo  (conv -> feature)
//      1=bias, write fp32               (preV / preU)
//      2=relu(bias + exCol[m]*exW[n*257]), write fp16 hi/lo  (seg layer0)
//      3=relu(bias), write fp32         (seg layer1)
template<int CONV, int EPI, int TP>
__global__ void __launch_bounds__(256, 2) mm_gemm(
    const __half* __restrict__ Ahi, const __half* __restrict__ Alo, int ldA,
    const __half* __restrict__ Bw, int ldB,
    const float* __restrict__ bias, const float* __restrict__ exCol,
    const float* __restrict__ exW,
    float* __restrict__ Cf, __half* __restrict__ Chi, __half* __restrict__ Clo,
    int N, int K)
{
    constexpr uint32_t STG  = TP ? 49152u : 32768u;   // stage bytes
    constexpr uint32_t BOFF = TP ? 32768u : 16384u;   // B offset within stage
    extern __shared__ __align__(128) char smem[];
    const int tid = threadIdx.x;
    const int m0 = blockIdx.y * 128;
    const int n0 = blockIdx.x * 128;
    const uint32_t sb = smem_u32(smem);
    const int NCH = K >> 6;

    const int lane = tid & 31, warp = tid >> 5;
    const int wm = (warp >> 2) * 64, wn = (warp & 3) * 32;
    const int rsel = lane & 15, ksel = lane >> 4;

    float acc[4][4][4];
#pragma unroll
    for (int i = 0; i < 4; i++)
#pragma unroll
        for (int j = 0; j < 4; j++)
#pragma unroll
            for (int u = 0; u < 4; u++) acc[i][j][u] = 0.f;

    auto issue_load = [&](int ch) {
        const int s = ch & 1;
        const int k0 = ch << 6;
        if (tid < 128) {
            const int row = tid;
            const __half *srcH, *srcL = nullptr;
            uint32_t sz = 16;
            if (CONV) {
                const int tap = k0 >> 12;
                const int coff = k0 & 4095;
                long sr = (long)m0 + row + tap - 1;
                const int tt = (row & 31) + tap - 1;
                if (tt < 0 || tt > 31) { sz = 0; sr = m0 + row; }
                srcH = Ahi + sr * ldA + coff;
                if (TP) srcL = Alo + sr * ldA + coff;
            } else {
                srcH = Ahi + (size_t)(m0 + row) * ldA + k0;
                if (TP) srcL = Alo + (size_t)(m0 + row) * ldA + k0;
            }
            const uint32_t d = sb + s * STG + row * 128;
            const int xm = row & 7;
#pragma unroll
            for (int c = 0; c < 8; c++) {
                const uint32_t cc = (uint32_t)((c ^ xm) << 4);
                cp16(d + cc, srcH + c * 8, sz);
                if (TP) cp16(d + 16384 + cc, srcL + c * 8, sz);
            }
        } else {
            const int row = tid - 128;
            const __half* srcB = Bw + (size_t)(n0 + row) * ldB + k0;
            const uint32_t d = sb + s * STG + BOFF + row * 128;
            const int xm = row & 7;
#pragma unroll
            for (int c = 0; c < 8; c++) {
                const uint32_t cc = (uint32_t)((c ^ xm) << 4);
                cp16(d + cc, srcB + c * 8, 16);
            }
        }
        asm volatile("cp.async.commit_group;" ::: "memory");
    };

    issue_load(0);
    for (int ch = 0; ch < NCH; ch++) {
        if (ch + 1 < NCH) issue_load(ch + 1);
        if (ch + 1 < NCH) asm volatile("cp.async.wait_group 1;" ::: "memory");
        else              asm volatile("cp.async.wait_group 0;" ::: "memory");
        __syncthreads();
        const uint32_t base = sb + (ch & 1) * STG;
#pragma unroll
        for (int ks = 0; ks < 4; ks++) {
            const int kc = ks * 2 + ksel;
            uint32_t ah[4][4], al[4][4];
#pragma unroll
            for (int im = 0; im < 4; im++) {
                const int row = wm + im * 16 + rsel;
                const uint32_t a = base + row * 128 + (uint32_t)(((kc ^ (row & 7))) << 4);
                ldm4(ah[im], a);
                if (TP) ldm4(al[im], a + 16384);
            }
            uint32_t bh[4][2];
#pragma unroll
            for (int j2 = 0; j2 < 2; j2++) {
                const int row = wn + j2 * 16 + rsel;
                const uint32_t a = base + BOFF + row * 128 + (uint32_t)(((kc ^ (row & 7))) << 4);
                uint32_t t[4];
                ldm4(t, a);
                bh[j2 * 2][0] = t[0]; bh[j2 * 2][1] = t[2];
                bh[j2 * 2 + 1][0] = t[1]; bh[j2 * 2 + 1][1] = t[3];
            }
#pragma unroll
            for (int im = 0; im < 4; im++)
#pragma unroll
                for (int jn = 0; jn < 4; jn++) {
                    mma16816(acc[im][jn], ah[im], bh[jn]);
                    if (TP) mma16816(acc[im][jn], al[im], bh[jn]);
                }
        }
        __syncthreads();
    }

    // ---- epilogue ----
    const int g = lane >> 2, t4 = lane & 3;
#pragma unroll
    for (int im = 0; im < 4; im++) {
#pragma unroll
        for (int jn = 0; jn < 4; jn++) {
            const int n = n0 + wn + jn * 8 + t4 * 2;
            const float bv0 = bias[n], bv1 = bias[n + 1];
            float ew0 = 0.f, ew1 = 0.f;
            if (EPI == 2) { ew0 = exW[(size_t)n * 257]; ew1 = exW[(size_t)(n + 1) * 257]; }
#pragma unroll
            for (int h = 0; h < 2; h++) {
                const int m = m0 + wm + im * 16 + g + h * 8;
                float v0 = acc[im][jn][h * 2 + 0] + bv0;
                float v1 = acc[im][jn][h * 2 + 1] + bv1;
                if (EPI == 2) {
                    const float ec = exCol[m];
                    v0 += ec * ew0; v1 += ec * ew1;
                }
                if (EPI >= 2) { v0 = fmaxf(v0, 0.f); v1 = fmaxf(v1, 0.f); }
                const size_t off = (size_t)m * N + n;
                if (EPI != 2)
                    *reinterpret_cast<float2*>(Cf + off) = make_float2(v0, v1);
                if (EPI == 0 || EPI == 2) {
                    __half h0, l0, h1, l1;
                    splith(v0, h0, l0); splith(v1, h1, l1);
                    __half2 ph, pl;
                    ph.x = h0; ph.y = h1; pl.x = l0; pl.y = l1;
                    *reinterpret_cast<__half2*>(Chi + off) = ph;
                    *reinterpret_cast<__half2*>(Clo + off) = pl;
                }
            }
        }
    }
}

// ======================= gated attention combine =======================
__global__ void __launch_bounds__(256) gated_kernel(
    const float* __restrict__ pv, const float* __restrict__ pu,
    const float* __restrict__ gw, const float* __restrict__ gb,
    float* __restrict__ Amat)
{
    int m = blockIdx.x * 8 + (threadIdx.x >> 5);
    int lane = threadIdx.x & 31;
    float acc = 0.f;
#pragma unroll
    for (int i = 0; i < 8; i++) {
        int d = lane + i * 32;
        float v = tanhf(pv[(size_t)m * 256 + d]);
        float u = 1.f / (1.f + expf(-pu[(size_t)m * 256 + d]));
        acc += v * u * gw[d];
    }
#pragma unroll
    for (int o = 16; o; o >>= 1) acc += __shfl_xor_sync(0xffffffffu, acc, o);
    if (lane == 0) Amat[m] = acc + gb[0];
}

// ======================= softmax over T + bag + At =======================
__global__ void __launch_bounds__(256) softbag_kernel(
    const float* __restrict__ Amat, const float* __restrict__ feat,
    float* __restrict__ bag, float* __restrict__ outAt)
{
    __shared__ float p[32];
    int b = blockIdx.x;
    int tid = threadIdx.x;
    if (tid < 32) {
        float v = Amat[b * 32 + tid];
        outAt[b * 32 + tid] = v;
        float mx = v;
#pragma unroll
        for (int o = 16; o; o >>= 1) mx = fmaxf(mx, __shfl_xor_sync(0xffffffffu, mx, o));
        float e = expf(v - mx);
        float s = e;
#pragma unroll
        for (int o = 16; o; o >>= 1) s += __shfl_xor_sync(0xffffffffu, s, o);
        p[tid] = e / s;
    }
    __syncthreads();
    float acc = 0.f;
#pragma unroll 8
    for (int t = 0; t < 32; t++) acc += p[t] * feat[(size_t)(b * 32 + t) * 256 + tid];
    bag[b * 256 + tid] = acc;
}

// ======================= bag classifier =======================
__global__ void __launch_bounds__(256) bagclf_kernel(
    const float* __restrict__ bag,
    const float* __restrict__ w0, const float* __restrict__ b0,
    const float* __restrict__ w1, const float* __restrict__ b1,
    const float* __restrict__ w2, const float* __restrict__ b2,
    const float* __restrict__ w3, const float* __restrict__ b3,
    float* __restrict__ outp)
{
    __shared__ float sb[8 * 256];
    __shared__ float sh[8 * 256];
    int base = blockIdx.x * 8;
    int tid = threadIdx.x;
#pragma unroll
    for (int i = 0; i < 8; i++) sb[tid + i * 256] = bag[(size_t)base * 256 + tid + i * 256];
    __syncthreads();
    {
        float acc[8] = {0, 0, 0, 0, 0, 0, 0, 0};
        const float* w = w0 + (size_t)tid * 256;
        for (int l = 0; l < 256; l++) {
            float wv = w[l];
#pragma unroll
            for (int r = 0; r < 8; r++) acc[r] += wv * sb[r * 256 + l];
        }
        float bb = b0[tid];
#pragma unroll
        for (int r = 0; r < 8; r++) sh[r * 256 + tid] = fmaxf(acc[r] + bb, 0.f);
    }
    __syncthreads();
    if (tid < 128) {
        float acc[8] = {0, 0, 0, 0, 0, 0, 0, 0};
        const float* w = w1 + (size_t)tid * 256;
        for (int l = 0; l < 256; l++) {
            float wv = w[l];
#pragma unroll
            for (int r = 0; r < 8; r++) acc[r] += wv * sh[r * 256 + l];
        }
        float bb = b1[tid];
#pragma unroll
        for (int r = 0; r < 8; r++) sb[r * 128 + tid] = fmaxf(acc[r] + bb, 0.f);
    }
    __syncthreads();
    if (tid < 32) {
        float acc[8] = {0, 0, 0, 0, 0, 0, 0, 0};
        const float* w = w2 + (size_t)tid * 128;
        for (int l = 0; l < 128; l++) {
            float wv = w[l];
#pragma unroll
            for (int r = 0; r < 8; r++) acc[r] += wv * sb[r * 128 + l];
        }
        float bb = b2[tid];
#pragma unroll
        for (int r = 0; r < 8; r++) sh[r * 32 + tid] = fmaxf(acc[r] + bb, 0.f);
    }
    __syncthreads();
    if (tid < 8) {
        float a = 0.f;
        for (int j = 0; j < 32; j++) a += w3[j] * sh[tid * 32 + j];
        float o1 = 1.f / (1.f + expf(-(a + b3[0])));
        outp[(size_t)(base + tid) * 2 + 0] = 0.5f * o1;
    }
}

// ======================= seg tail =======================
__global__ void __launch_bounds__(256) segtail_kernel(
    const float* __restrict__ h1,
    const float* __restrict__ w2, const float* __restrict__ b2,
    const float* __restrict__ w3, const float* __restrict__ b3,
    float* __restrict__ out_seg)
{
    __shared__ float sw2[128 * 32];
    __shared__ float sh1[8 * 128];
    int m0 = blockIdx.x * 8;
    int tid = threadIdx.x;
#pragma unroll
    for (int i = 0; i < 16; i++) {
        int idx = tid + i * 256;
        sw2[(idx & 127) * 32 + (idx >> 7)] = w2[idx];
    }
#pragma unroll
    for (int i = 0; i < 4; i++) {
        int idx = tid + i * 256;
        sh1[idx] = h1[(size_t)m0 * 128 + idx];
    }
    __syncthreads();
    int r = tid >> 5, j = tid & 31;
    float acc = b2[j];
#pragma unroll 8
    for (int l = 0; l < 128; l++) acc += sw2[l * 32 + j] * sh1[r * 128 + l];
    float h2 = fmaxf(acc, 0.f);
    float v = h2 * w3[j];
#pragma unroll
    for (int o = 16; o; o >>= 1) v += __shfl_xor_sync(0xffffffffu, v, o);
    if (j == 0) out_seg[m0 + r] = 1.f / (1.f + expf(-(v + b3[0])));
}

// ======================= per-sample 2-means (cosine) =======================
__global__ void __launch_bounds__(256) kmeans_kernel(
    const float* __restrict__ feat, const float* __restrict__ seg,
    float* __restrict__ out_assign, float* __restrict__ out_pair)
{
    __shared__ float sf[32 * 256];
    __shared__ float sc[2 * 256];
    __shared__ float scn[2 * 256];
    __shared__ int sassign[32];
    __shared__ int s_ctrl[3];
    int b = blockIdx.x;
    int tid = threadIdx.x;
    int lane = tid & 31, w = tid >> 5;

#pragma unroll
    for (int i = 0; i < 32; i++) sf[tid + i * 256] = feat[(size_t)b * 8192 + tid + i * 256];
    sc[tid] = sf[tid];
    sc[256 + tid] = sf[4096 + tid];
    if (tid == 0) s_ctrl[2] = 0;
    __syncthreads();

    int final_mask = 0;
    for (int it = 0; it < 100; it++) {
        if (w < 2) {
            float s = 0.f;
#pragma unroll
            for (int i = 0; i < 8; i++) {
                float v = sc[w * 256 + lane + i * 32];
                s += v * v;
            }
#pragma unroll
            for (int o = 16; o; o >>= 1) s += __shfl_xor_sync(0xffffffffu, s, o);
            float inv = 1.f / (sqrtf(s) + 1e-8f);
#pragma unroll
            for (int i = 0; i < 8; i++)
                scn[w * 256 + lane + i * 32] = sc[w * 256 + lane + i * 32] * inv;
        }
        __syncthreads();
#pragma unroll
        for (int p = 0; p < 4; p++) {
            int t = w * 4 + p;
            float s0 = 0.f, s1 = 0.f;
#pragma unroll
            for (int i = 0; i < 8; i++) {
                float fv = sf[t * 256 + lane + i * 32];
                s0 += fv * scn[lane + i * 32];
                s1 += fv * scn[256 + lane + i * 32];
            }
#pragma unroll
            for (int o = 16; o; o >>= 1) {
                s0 += __shfl_xor_sync(0xffffffffu, s0, o);
                s1 += __shfl_xor_sync(0xffffffffu, s1, o);
            }
            if (lane == 0) sassign[t] = (s1 > s0) ? 1 : 0;
        }
        __syncthreads();
        if (tid == 0) {
            int mask = 0;
#pragma unroll
            for (int t = 0; t < 32; t++) mask |= sassign[t] << t;
            s_ctrl[0] = mask;
            s_ctrl[1] = (it > 0 && mask == s_ctrl[2]) ? 1 : 0;
            s_ctrl[2] = mask;
        }
        __syncthreads();
        int mask = s_ctrl[0];
        final_mask = mask;
        if (s_ctrl[1]) break;
        int cnt1 = __popc(mask);
        int cnt0 = 32 - cnt1;
        float a0 = 0.f, a1 = 0.f;
#pragma unroll
        for (int t = 0; t < 32; t++) {
            float fv = sf[t * 256 + tid];
            if ((mask >> t) & 1) a1 += fv; else a0 += fv;
        }
        if (cnt0 > 0) sc[tid] = a0 / (float)cnt0;
        if (cnt1 > 0) sc[256 + tid] = a1 / (float)cnt1;
        __syncthreads();
    }

    if (tid < 32) {
        int bit = (final_mask >> tid) & 1;
        out_assign[b * 32 + tid] = (float)bit;
        float s = seg[b * 32 + tid];
        float v0 = bit ? 0.f : s;
        float v1 = bit ? s : 0.f;
#pragma unroll
        for (int o = 16; o; o >>= 1) {
            v0 += __shfl_xor_sync(0xffffffffu, v0, o);
            v1 += __shfl_xor_sync(0xffffffffu, v1, o);
        }
        int cnt1 = __popc(final_mask);
        int cnt0 = 32 - cnt1;
        float m0 = (cnt0 > 0) ? v0 / (float)cnt0 : -INFINITY;
        float m1 = (cnt1 > 0) ? v1 / (float)cnt1 : -INFINITY;
        if (tid == 0) out_pair[(size_t)b * 2 + 1] = 0.5f * fmaxf(m0, m1);
    }
}

// ======================= launch =======================
extern "C" void kernel_launch(void* const* d_in, const int* in_sizes, int n_in,
                              void* d_out, int out_size)
{
    const float* x      = (const float*)d_in[0];
    const float* tsn_w  = (const float*)d_in[1];
    const float* tsn_b  = (const float*)d_in[2];
    const float* aV_w   = (const float*)d_in[3];
    const float* aV_b   = (const float*)d_in[4];
    const float* aU_w   = (const float*)d_in[5];
    const float* aU_b   = (const float*)d_in[6];
    const float* gate_w = (const float*)d_in[7];
    const float* gate_b = (const float*)d_in[8];
    const float* cb_w0 = (const float*)d_in[9],  *cb_b0 = (const float*)d_in[10];
    const float* cb_w1 = (const float*)d_in[11], *cb_b1 = (const float*)d_in[12];
    const float* cb_w2 = (const float*)d_in[13], *cb_b2 = (const float*)d_in[14];
    const float* cb_w3 = (const float*)d_in[15], *cb_b3 = (const float*)d_in[16];
    const float* cs_w0 = (const float*)d_in[17], *cs_b0 = (const float*)d_in[18];
    const float* cs_w1 = (const float*)d_in[19], *cs_b1 = (const float*)d_in[20];
    const float* cs_w2 = (const float*)d_in[21], *cs_b2 = (const float*)d_in[22];
    const float* cs_w3 = (const float*)d_in[23], *cs_b3 = (const float*)d_in[24];

    float* out = (float*)d_out;
    float* feat    = out + OFF_FEAT;
    float* oAssign = out + OFF_ASSIGN;
    float* oSeg    = out + OFF_SEG;
    float* oOut    = out + OFF_OUT;
    float* oAt     = out + OFF_AT;

    __half *xh, *wt, *bw, *fhi, *flo, *h0hi, *h0lo;
    float *preV, *preU, *Amat, *bag, *h1;
    cudaGetSymbolAddress((void**)&xh, g_xh);
    cudaGetSymbolAddress((void**)&wt, g_wt);     cudaGetSymbolAddress((void**)&bw, g_bw);
    cudaGetSymbolAddress((void**)&fhi, g_fhi);   cudaGetSymbolAddress((void**)&flo, g_flo);
    cudaGetSymbolAddress((void**)&h0hi, g_h0hi); cudaGetSymbolAddress((void**)&h0lo, g_h0lo);
    cudaGetSymbolAddress((void**)&preV, g_preV); cudaGetSymbolAddress((void**)&preU, g_preU);
    cudaGetSymbolAddress((void**)&Amat, g_Amat); cudaGetSymbolAddress((void**)&bag, g_bag);
    cudaGetSymbolAddress((void**)&h1, g_h1);

    const int SMB1 = 2 * 32768;   // single-pass stages (conv)
    const int SMB2 = 2 * 49152;   // two-pass stages
    cudaFuncSetAttribute(mm_gemm<1, 0, 0>, cudaFuncAttributeMaxDynamicSharedMemorySize, SMB1);
    cudaFuncSetAttribute(mm_gemm<0, 1, 1>, cudaFuncAttributeMaxDynamicSharedMemorySize, SMB2);
    cudaFuncSetAttribute(mm_gemm<0, 2, 1>, cudaFuncAttributeMaxDynamicSharedMemorySize, SMB2);
    cudaFuncSetAttribute(mm_gemm<0, 3, 1>, cudaFuncAttributeMaxDynamicSharedMemorySize, SMB2);

    // converts / repacks
    conv_x_k<<<65536, 256>>>((const float4*)x, (__half2*)xh);
    splitw_conv_k<<<(L_ * KCONV) / 256, 256>>>(tsn_w, wt);
    splitw_gen_k<<<256, 256>>>(aV_w, 256, 65536, bw);
    splitw_gen_k<<<256, 256>>>(aU_w, 256, 65536, bw + 65536);
    splitw_gen_k<<<256, 256>>>(cs_w0, 257, 65536, bw + 131072);
    splitw_gen_k<<<128, 256>>>(cs_w1, 256, 32768, bw + 196608);

    // conv-as-GEMM (single fp16 pass) -> feature fp32 + fhi/flo
    mm_gemm<1, 0, 0><<<dim3(2, 128), 256, SMB1>>>(xh, nullptr, FIN, wt, KCONV,
                                                  tsn_b, nullptr, nullptr,
                                                  feat, fhi, flo, 256, KCONV);
    // attention projections (2-pass, feature hi/lo)
    mm_gemm<0, 1, 1><<<dim3(2, 128), 256, SMB2>>>(fhi, flo, 256, bw, 256,
                                                  aV_b, nullptr, nullptr,
                                                  preV, nullptr, nullptr, 256, 256);
    mm_gemm<0, 1, 1><<<dim3(2, 128), 256, SMB2>>>(fhi, flo, 256, bw + 65536, 256,
                                                  aU_b, nullptr, nullptr,
                                                  preU, nullptr, nullptr, 256, 256);
    // gated combine + softmax/bag + bag classifier
    gated_kernel<<<M_ / 8, 256>>>(preV, preU, gate_w, gate_b, Amat);
    softbag_kernel<<<B_, 256>>>(Amat, feat, bag, oAt);
    bagclf_kernel<<<B_ / 8, 256>>>(bag, cb_w0, cb_b0, cb_w1, cb_b1,
                                   cb_w2, cb_b2, cb_w3, cb_b3, oOut);
    // seg classifier
    mm_gemm<0, 2, 1><<<dim3(2, 128), 256, SMB2>>>(fhi, flo, 256, bw + 131072, 256,
                                                  cs_b0, Amat, cs_w0 + 256,
                                                  nullptr, h0hi, h0lo, 256, 256);
    mm_gemm<0, 3, 1><<<dim3(1, 128), 256, SMB2>>>(h0hi, h0lo, 256, bw + 196608, 256,
                                                  cs_b1, nullptr, nullptr,
                                                  h1, nullptr, nullptr, 128, 256);
    segtail_kernel<<<M_ / 8, 256>>>(h1, cs_w2, cs_b2, cs_w3, cs_b3, oSeg);
    // 2-means -> assigns + output[:,1]
    kmeans_kernel<<<B_, 256>>>(feat, oSeg, oAssign, oOut);
}

// round 7
// speedup vs baseline: 3.1377x; 1.0105x over previous
#include <cuda_runtime.h>
#include <cuda_fp16.h>
#include <math.h>
#include <stdint.h>

#define B_   512
#define T_   32
#define FIN  4096
#define L_   256
#define M_   (B_*T_)
#define KCONV (3*FIN)

#define OFF_FEAT   0
#define OFF_ASSIGN 4194304
#define OFF_SEG    4210688
#define OFF_OUT    4227072
#define OFF_AT     4228096

// -------- scratch (device globals) --------
__device__ __align__(16) __half g_xh[(size_t)M_ * FIN];      // x fp16
__device__ __align__(16) __half g_wt[(size_t)L_ * KCONV];    // conv weight fp16 [n][k]
__device__ __align__(16) __half g_bw[229376];                // aV|aU|cs0|cs1 fp16 [n][256]
__device__ __align__(16) __half g_fhi[(size_t)M_ * L_];
__device__ __align__(16) __half g_flo[(size_t)M_ * L_];
__device__ __align__(16) __half g_h0hi[(size_t)M_ * 256];
__device__ __align__(16) __half g_h0lo[(size_t)M_ * 256];
__device__ float g_preVU[(size_t)M_ * 512];                  // [m][0:256)=V, [256:512)=U
__device__ float g_Amat[M_];
__device__ float g_bag[B_ * L_];
__device__ float g_h1[(size_t)M_ * 128];

// ======================= helpers =======================
__device__ __forceinline__ void splith(float v, __half& h, __half& l) {
    h = __float2half(v);
    l = __float2half(v - __half2float(h));
}
__device__ __forceinline__ uint32_t smem_u32(const void* p) {
    uint32_t a;
    asm("{ .reg .u64 t; cvta.to.shared.u64 t, %1; cvt.u32.u64 %0, t; }" : "=r"(a) : "l"(p));
    return a;
}
__device__ __forceinline__ void cp16(uint32_t dst, const void* src, uint32_t sz) {
    asm volatile("cp.async.cg.shared.global [%0], [%1], 16, %2;"
                 :: "r"(dst), "l"(src), "r"(sz) : "memory");
}
__device__ __forceinline__ void ldm4(uint32_t* r, uint32_t addr) {
    asm volatile("ldmatrix.sync.aligned.m8n8.x4.shared.b16 {%0,%1,%2,%3}, [%4];"
                 : "=r"(r[0]), "=r"(r[1]), "=r"(r[2]), "=r"(r[3]) : "r"(addr));
}
__device__ __forceinline__ void mma16816(float* c, const uint32_t* a, const uint32_t* b) {
    asm volatile("mma.sync.aligned.m16n8k16.row.col.f32.f16.f16.f32 "
                 "{%0,%1,%2,%3}, {%4,%5,%6,%7}, {%8,%9}, {%0,%1,%2,%3};"
                 : "+f"(c[0]), "+f"(c[1]), "+f"(c[2]), "+f"(c[3])
                 : "r"(a[0]), "r"(a[1]), "r"(a[2]), "r"(a[3]), "r"(b[0]), "r"(b[1]));
}
__device__ __forceinline__ float tanh_fast(float x) {
    float r;
    asm("tanh.approx.f32 %0, %1;" : "=f"(r) : "f"(x));
    return r;
}

// ======================= convert / repack kernels =======================
__global__ void conv_x_k(const float4* __restrict__ x, __half2* __restrict__ o) {
    size_t i = (size_t)blockIdx.x * 256 + threadIdx.x;
    float4 v = x[i];
    __half2 a, b;
    a.x = __float2half(v.x); a.y = __float2half(v.y);
    b.x = __float2half(v.z); b.y = __float2half(v.w);
    o[2 * i] = a; o[2 * i + 1] = b;
}

__global__ void splitw_conv_k(const float* __restrict__ w, __half* __restrict__ o) {
    int idx = blockIdx.x * 256 + threadIdx.x;          // [n][k], k = tap*4096 + c
    int n = idx / KCONV;
    int k = idx - n * KCONV;
    int tap = k >> 12, c = k & 4095;
    o[idx] = __float2half(w[(size_t)n * KCONV + c * 3 + tap]);
}

__global__ void splitw_pair_k(const float* __restrict__ wa, const float* __restrict__ wb,
                              __half* __restrict__ o) {
    int idx = blockIdx.x * 256 + threadIdx.x;          // 131072 total
    const float* w = (idx < 65536) ? wa : wb;
    int li = idx & 65535;
    o[idx] = __float2half(w[li]);
}

__global__ void splitw_gen_k(const float* __restrict__ w, int srcStride, int total,
                             __half* __restrict__ o) {
    int idx = blockIdx.x * 256 + threadIdx.x;
    if (idx >= total) return;
    int n = idx >> 8, k = idx & 255;
    o[idx] = __float2half(w[(size_t)n * srcStride + k]);
}

// ======================= HMMA GEMM (mma.sync fp16) =======================
// D[m][n] = epi( sum_k A[m][k]*B[n][k] + bias )
// TP=1: A hi/lo fp16 pair, 2 passes.  TP=0: single fp16, 1 pass.
// EPI: 0=bias, write fp32 + fp16 hi/lo   (conv -> feature)
//      2=relu(bias + exCol[m]*exW[n*257]), write fp16 hi/lo  (seg layer0)
//      3=relu(bias), write fp32          (seg layer1)
//      4=dual bias (n<256: bias[n], else exCol[n-256]), write fp32  (fused aV|aU)
template<int CONV, int EPI, int TP>
__global__ void __launch_bounds__(256, 2) mm_gemm(
    const __half* __restrict__ Ahi, const __half* __restrict__ Alo, int ldA,
    const __half* __restrict__ Bw, int ldB,
    const float* __restrict__ bias, const float* __restrict__ exCol,
    const float* __restrict__ exW,
    float* __restrict__ Cf, __half* __restrict__ Chi, __half* __restrict__ Clo,
    int N, int K)
{
    constexpr uint32_t STG  = TP ? 49152u : 32768u;
    constexpr uint32_t BOFF = TP ? 32768u : 16384u;
    extern __shared__ __align__(128) char smem[];
    const int tid = threadIdx.x;
    const int m0 = blockIdx.y * 128;
    const int n0 = blockIdx.x * 128;
    const uint32_t sb = smem_u32(smem);
    const int NCH = K >> 6;

    const int lane = tid & 31, warp = tid >> 5;
    const int wm = (warp >> 2) * 64, wn = (warp & 3) * 32;
    const int rsel = lane & 15, ksel = lane >> 4;

    float acc[4][4][4];
#pragma unroll
    for (int i = 0; i < 4; i++)
#pragma unroll
        for (int j = 0; j < 4; j++)
#pragma unroll
            for (int u = 0; u < 4; u++) acc[i][j][u] = 0.f;

    auto issue_load = [&](int ch) {
        const int s = ch & 1;
        const int k0 = ch << 6;
        if (tid < 128) {
            const int row = tid;
            const __half *srcH, *srcL = nullptr;
            uint32_t sz = 16;
            if (CONV) {
                const int tap = k0 >> 12;
                const int coff = k0 & 4095;
                long sr = (long)m0 + row + tap - 1;
                const int tt = (row & 31) + tap - 1;
                if (tt < 0 || tt > 31) { sz = 0; sr = m0 + row; }
                srcH = Ahi + sr * ldA + coff;
                if (TP) srcL = Alo + sr * ldA + coff;
            } else {
                srcH = Ahi + (size_t)(m0 + row) * ldA + k0;
                if (TP) srcL = Alo + (size_t)(m0 + row) * ldA + k0;
            }
            const uint32_t d = sb + s * STG + row * 128;
            const int xm = row & 7;
#pragma unroll
            for (int c = 0; c < 8; c++) {
                const uint32_t cc = (uint32_t)((c ^ xm) << 4);
                cp16(d + cc, srcH + c * 8, sz);
                if (TP) cp16(d + 16384 + cc, srcL + c * 8, sz);
            }
        } else {
            const int row = tid - 128;
            const __half* srcB = Bw + (size_t)(n0 + row) * ldB + k0;
            const uint32_t d = sb + s * STG + BOFF + row * 128;
            const int xm = row & 7;
#pragma unroll
            for (int c = 0; c < 8; c++) {
                const uint32_t cc = (uint32_t)((c ^ xm) << 4);
                cp16(d + cc, srcB + c * 8, 16);
            }
        }
        asm volatile("cp.async.commit_group;" ::: "memory");
    };

    issue_load(0);
    for (int ch = 0; ch < NCH; ch++) {
        if (ch + 1 < NCH) issue_load(ch + 1);
        if (ch + 1 < NCH) asm volatile("cp.async.wait_group 1;" ::: "memory");
        else              asm volatile("cp.async.wait_group 0;" ::: "memory");
        __syncthreads();
        const uint32_t base = sb + (ch & 1) * STG;
#pragma unroll
        for (int ks = 0; ks < 4; ks++) {
            const int kc = ks * 2 + ksel;
            uint32_t ah[4][4], al[4][4];
#pragma unroll
            for (int im = 0; im < 4; im++) {
                const int row = wm + im * 16 + rsel;
                const uint32_t a = base + row * 128 + (uint32_t)(((kc ^ (row & 7))) << 4);
                ldm4(ah[im], a);
                if (TP) ldm4(al[im], a + 16384);
            }
            uint32_t bh[4][2];
#pragma unroll
            for (int j2 = 0; j2 < 2; j2++) {
                const int row = wn + j2 * 16 + rsel;
                const uint32_t a = base + BOFF + row * 128 + (uint32_t)(((kc ^ (row & 7))) << 4);
                uint32_t t[4];
                ldm4(t, a);
                bh[j2 * 2][0] = t[0]; bh[j2 * 2][1] = t[2];
                bh[j2 * 2 + 1][0] = t[1]; bh[j2 * 2 + 1][1] = t[3];
            }
#pragma unroll
            for (int im = 0; im < 4; im++)
#pragma unroll
                for (int jn = 0; jn < 4; jn++) {
                    mma16816(acc[im][jn], ah[im], bh[jn]);
                    if (TP) mma16816(acc[im][jn], al[im], bh[jn]);
                }
        }
        __syncthreads();
    }

    // ---- epilogue ----
    const int g = lane >> 2, t4 = lane & 3;
#pragma unroll
    for (int im = 0; im < 4; im++) {
#pragma unroll
        for (int jn = 0; jn < 4; jn++) {
            const int n = n0 + wn + jn * 8 + t4 * 2;
            float bv0, bv1;
            if (EPI == 4) {
                bv0 = (n < 256) ? bias[n] : exCol[n - 256];
                bv1 = (n + 1 < 256) ? bias[n + 1] : exCol[n + 1 - 256];
            } else {
                bv0 = bias[n]; bv1 = bias[n + 1];
            }
            float ew0 = 0.f, ew1 = 0.f;
            if (EPI == 2) { ew0 = exW[(size_t)n * 257]; ew1 = exW[(size_t)(n + 1) * 257]; }
#pragma unroll
            for (int h = 0; h < 2; h++) {
                const int m = m0 + wm + im * 16 + g + h * 8;
                float v0 = acc[im][jn][h * 2 + 0] + bv0;
                float v1 = acc[im][jn][h * 2 + 1] + bv1;
                if (EPI == 2) {
                    const float ec = exCol[m];
                    v0 += ec * ew0; v1 += ec * ew1;
                }
                if (EPI == 2 || EPI == 3) { v0 = fmaxf(v0, 0.f); v1 = fmaxf(v1, 0.f); }
                const size_t off = (size_t)m * N + n;
                if (EPI != 2)
                    *reinterpret_cast<float2*>(Cf + off) = make_float2(v0, v1);
                if (EPI == 0 || EPI == 2) {
                    __half h0, l0, h1, l1;
                    splith(v0, h0, l0); splith(v1, h1, l1);
                    __half2 ph, pl;
                    ph.x = h0; ph.y = h1; pl.x = l0; pl.y = l1;
                    *reinterpret_cast<__half2*>(Chi + off) = ph;
                    *reinterpret_cast<__half2*>(Clo + off) = pl;
                }
            }
        }
    }
}

// ======================= gated attention combine (approx math) =======================
__global__ void __launch_bounds__(256) gated_kernel(
    const float* __restrict__ pvu,
    const float* __restrict__ gw, const float* __restrict__ gb,
    float* __restrict__ Amat)
{
    int m = blockIdx.x * 8 + (threadIdx.x >> 5);
    int lane = threadIdx.x & 31;
    const float* row = pvu + (size_t)m * 512;
    float acc = 0.f;
#pragma unroll
    for (int i = 0; i < 8; i++) {
        int d = lane + i * 32;
        float v = tanh_fast(row[d]);
        float u = __fdividef(1.f, 1.f + __expf(-row[256 + d]));
        acc += v * u * gw[d];
    }
#pragma unroll
    for (int o = 16; o; o >>= 1) acc += __shfl_xor_sync(0xffffffffu, acc, o);
    if (lane == 0) Amat[m] = acc + gb[0];
}

// ======================= softmax over T + bag + At =======================
__global__ void __launch_bounds__(256) softbag_kernel(
    const float* __restrict__ Amat, const float* __restrict__ feat,
    float* __restrict__ bag, float* __restrict__ outAt)
{
    __shared__ float p[32];
    int b = blockIdx.x;
    int tid = threadIdx.x;
    if (tid < 32) {
        float v = Amat[b * 32 + tid];
        outAt[b * 32 + tid] = v;
        float mx = v;
#pragma unroll
        for (int o = 16; o; o >>= 1) mx = fmaxf(mx, __shfl_xor_sync(0xffffffffu, mx, o));
        float e = expf(v - mx);
        float s = e;
#pragma unroll
        for (int o = 16; o; o >>= 1) s += __shfl_xor_sync(0xffffffffu, s, o);
        p[tid] = e / s;
    }
    __syncthreads();
    float acc = 0.f;
#pragma unroll 8
    for (int t = 0; t < 32; t++) acc += p[t] * feat[(size_t)(b * 32 + t) * 256 + tid];
    bag[b * 256 + tid] = acc;
}

// ======================= bag classifier =======================
__global__ void __launch_bounds__(256) bagclf_kernel(
    const float* __restrict__ bag,
    const float* __restrict__ w0, const float* __restrict__ b0,
    const float* __restrict__ w1, const float* __restrict__ b1,
    const float* __restrict__ w2, const float* __restrict__ b2,
    const float* __restrict__ w3, const float* __restrict__ b3,
    float* __restrict__ outp)
{
    __shared__ float sb[8 * 256];
    __shared__ float sh[8 * 256];
    int base = blockIdx.x * 8;
    int tid = threadIdx.x;
#pragma unroll
    for (int i = 0; i < 8; i++) sb[tid + i * 256] = bag[(size_t)base * 256 + tid + i * 256];
    __syncthreads();
    {
        float acc[8] = {0, 0, 0, 0, 0, 0, 0, 0};
        const float* w = w0 + (size_t)tid * 256;
        for (int l = 0; l < 256; l++) {
            float wv = w[l];
#pragma unroll
            for (int r = 0; r < 8; r++) acc[r] += wv * sb[r * 256 + l];
        }
        float bb = b0[tid];
#pragma unroll
        for (int r = 0; r < 8; r++) sh[r * 256 + tid] = fmaxf(acc[r] + bb, 0.f);
    }
    __syncthreads();
    if (tid < 128) {
        float acc[8] = {0, 0, 0, 0, 0, 0, 0, 0};
        const float* w = w1 + (size_t)tid * 256;
        for (int l = 0; l < 256; l++) {
            float wv = w[l];
#pragma unroll
            for (int r = 0; r < 8; r++) acc[r] += wv * sh[r * 256 + l];
        }
        float bb = b1[tid];
#pragma unroll
        for (int r = 0; r < 8; r++) sb[r * 128 + tid] = fmaxf(acc[r] + bb, 0.f);
    }
    __syncthreads();
    if (tid < 32) {
        float acc[8] = {0, 0, 0, 0, 0, 0, 0, 0};
        const float* w = w2 + (size_t)tid * 128;
        for (int l = 0; l < 128; l++) {
            float wv = w[l];
#pragma unroll
            for (int r = 0; r < 8; r++) acc[r] += wv * sb[r * 128 + l];
        }
        float bb = b2[tid];
#pragma unroll
        for (int r = 0; r < 8; r++) sh[r * 32 + tid] = fmaxf(acc[r] + bb, 0.f);
    }
    __syncthreads();
    if (tid < 8) {
        float a = 0.f;
        for (int j = 0; j < 32; j++) a += w3[j] * sh[tid * 32 + j];
        float o1 = 1.f / (1.f + expf(-(a + b3[0])));
        outp[(size_t)(base + tid) * 2 + 0] = 0.5f * o1;
    }
}

// ======================= seg tail =======================
__global__ void __launch_bounds__(256) segtail_kernel(
    const float* __restrict__ h1,
    const float* __restrict__ w2, const float* __restrict__ b2,
    const float* __restrict__ w3, const float* __restrict__ b3,
    float* __restrict__ out_seg)
{
    __shared__ float sw2[128 * 32];
    __shared__ float sh1[8 * 128];
    int m0 = blockIdx.x * 8;
    int tid = threadIdx.x;
#pragma unroll
    for (int i = 0; i < 16; i++) {
        int idx = tid + i * 256;
        sw2[(idx & 127) * 32 + (idx >> 7)] = w2[idx];
    }
#pragma unroll
    for (int i = 0; i < 4; i++) {
        int idx = tid + i * 256;
        sh1[idx] = h1[(size_t)m0 * 128 + idx];
    }
    __syncthreads();
    int r = tid >> 5, j = tid & 31;
    float acc = b2[j];
#pragma unroll 8
    for (int l = 0; l < 128; l++) acc += sw2[l * 32 + j] * sh1[r * 128 + l];
    float h2 = fmaxf(acc, 0.f);
    float v = h2 * w3[j];
#pragma unroll
    for (int o = 16; o; o >>= 1) v += __shfl_xor_sync(0xffffffffu, v, o);
    if (j == 0) out_seg[m0 + r] = 1.f / (1.f + expf(-(v + b3[0])));
}

// ======================= per-sample 2-means (cosine, sign-test) =======================
__global__ void __launch_bounds__(256) kmeans_kernel(
    const float* __restrict__ feat, const float* __restrict__ seg,
    float* __restrict__ out_assign, float* __restrict__ out_pair)
{
    __shared__ float sf[32 * 256];
    __shared__ float sc[2 * 256];
    __shared__ float sdiff[256];
    __shared__ float sinv[2];
    __shared__ int sassign[32];
    __shared__ int s_ctrl[3];
    int b = blockIdx.x;
    int tid = threadIdx.x;
    int lane = tid & 31, w = tid >> 5;

#pragma unroll
    for (int i = 0; i < 32; i++) sf[tid + i * 256] = feat[(size_t)b * 8192 + tid + i * 256];
    sc[tid] = sf[tid];
    sc[256 + tid] = sf[4096 + tid];
    if (tid == 0) s_ctrl[2] = 0;
    __syncthreads();

    int final_mask = 0;
    for (int it = 0; it < 100; it++) {
        // center inverse norms (warps 0,1)
        if (w < 2) {
            float s = 0.f;
#pragma unroll
            for (int i = 0; i < 8; i++) {
                float v = sc[w * 256 + lane + i * 32];
                s += v * v;
            }
#pragma unroll
            for (int o = 16; o; o >>= 1) s += __shfl_xor_sync(0xffffffffu, s, o);
            if (lane == 0) sinv[w] = 1.f / (sqrtf(s) + 1e-8f);
        }
        __syncthreads();
        // normalized-center difference (sign test: assign1 iff f·diff > 0)
        sdiff[tid] = sc[256 + tid] * sinv[1] - sc[tid] * sinv[0];
        __syncthreads();
#pragma unroll
        for (int p = 0; p < 4; p++) {
            int t = w * 4 + p;
            float s = 0.f;
#pragma unroll
            for (int i = 0; i < 8; i++)
                s += sf[t * 256 + lane + i * 32] * sdiff[lane + i * 32];
#pragma unroll
            for (int o = 16; o; o >>= 1) s += __shfl_xor_sync(0xffffffffu, s, o);
            if (lane == 0) sassign[t] = (s > 0.f) ? 1 : 0;
        }
        __syncthreads();
        if (tid == 0) {
            int mask = 0;
#pragma unroll
            for (int t = 0; t < 32; t++) mask |= sassign[t] << t;
            s_ctrl[0] = mask;
            s_ctrl[1] = (it > 0 && mask == s_ctrl[2]) ? 1 : 0;
            s_ctrl[2] = mask;
        }
        __syncthreads();
        int mask = s_ctrl[0];
        final_mask = mask;
        if (s_ctrl[1]) break;
        int cnt1 = __popc(mask);
        int cnt0 = 32 - cnt1;
        float a0 = 0.f, a1 = 0.f;
#pragma unroll
        for (int t = 0; t < 32; t++) {
            float fv = sf[t * 256 + tid];
            if ((mask >> t) & 1) a1 += fv; else a0 += fv;
        }
        if (cnt0 > 0) sc[tid] = a0 / (float)cnt0;
        if (cnt1 > 0) sc[256 + tid] = a1 / (float)cnt1;
        __syncthreads();
    }

    if (tid < 32) {
        int bit = (final_mask >> tid) & 1;
        out_assign[b * 32 + tid] = (float)bit;
        float s = seg[b * 32 + tid];
        float v0 = bit ? 0.f : s;
        float v1 = bit ? s : 0.f;
#pragma unroll
        for (int o = 16; o; o >>= 1) {
            v0 += __shfl_xor_sync(0xffffffffu, v0, o);
            v1 += __shfl_xor_sync(0xffffffffu, v1, o);
        }
        int cnt1 = __popc(final_mask);
        int cnt0 = 32 - cnt1;
        float m0 = (cnt0 > 0) ? v0 / (float)cnt0 : -INFINITY;
        float m1 = (cnt1 > 0) ? v1 / (float)cnt1 : -INFINITY;
        if (tid == 0) out_pair[(size_t)b * 2 + 1] = 0.5f * fmaxf(m0, m1);
    }
}

// ======================= launch =======================
extern "C" void kernel_launch(void* const* d_in, const int* in_sizes, int n_in,
                              void* d_out, int out_size)
{
    const float* x      = (const float*)d_in[0];
    const float* tsn_w  = (const float*)d_in[1];
    const float* tsn_b  = (const float*)d_in[2];
    const float* aV_w   = (const float*)d_in[3];
    const float* aV_b   = (const float*)d_in[4];
    const float* aU_w   = (const float*)d_in[5];
    const float* aU_b   = (const float*)d_in[6];
    const float* gate_w = (const float*)d_in[7];
    const float* gate_b = (const float*)d_in[8];
    const float* cb_w0 = (const float*)d_in[9],  *cb_b0 = (const float*)d_in[10];
    const float* cb_w1 = (const float*)d_in[11], *cb_b1 = (const float*)d_in[12];
    const float* cb_w2 = (const float*)d_in[13], *cb_b2 = (const float*)d_in[14];
    const float* cb_w3 = (const float*)d_in[15], *cb_b3 = (const float*)d_in[16];
    const float* cs_w0 = (const float*)d_in[17], *cs_b0 = (const float*)d_in[18];
    const float* cs_w1 = (const float*)d_in[19], *cs_b1 = (const float*)d_in[20];
    const float* cs_w2 = (const float*)d_in[21], *cs_b2 = (const float*)d_in[22];
    const float* cs_w3 = (const float*)d_in[23], *cs_b3 = (const float*)d_in[24];

    float* out = (float*)d_out;
    float* feat    = out + OFF_FEAT;
    float* oAssign = out + OFF_ASSIGN;
    float* oSeg    = out + OFF_SEG;
    float* oOut    = out + OFF_OUT;
    float* oAt     = out + OFF_AT;

    __half *xh, *wt, *bw, *fhi, *flo, *h0hi, *h0lo;
    float *preVU, *Amat, *bag, *h1;
    cudaGetSymbolAddress((void**)&xh, g_xh);
    cudaGetSymbolAddress((void**)&wt, g_wt);     cudaGetSymbolAddress((void**)&bw, g_bw);
    cudaGetSymbolAddress((void**)&fhi, g_fhi);   cudaGetSymbolAddress((void**)&flo, g_flo);
    cudaGetSymbolAddress((void**)&h0hi, g_h0hi); cudaGetSymbolAddress((void**)&h0lo, g_h0lo);
    cudaGetSymbolAddress((void**)&preVU, g_preVU);
    cudaGetSymbolAddress((void**)&Amat, g_Amat); cudaGetSymbolAddress((void**)&bag, g_bag);
    cudaGetSymbolAddress((void**)&h1, g_h1);

    const int SMB1 = 2 * 32768;
    const int SMB2 = 2 * 49152;
    cudaFuncSetAttribute(mm_gemm<1, 0, 0>, cudaFuncAttributeMaxDynamicSharedMemorySize, SMB1);
    cudaFuncSetAttribute(mm_gemm<0, 4, 1>, cudaFuncAttributeMaxDynamicSharedMemorySize, SMB2);
    cudaFuncSetAttribute(mm_gemm<0, 2, 1>, cudaFuncAttributeMaxDynamicSharedMemorySize, SMB2);
    cudaFuncSetAttribute(mm_gemm<0, 3, 1>, cudaFuncAttributeMaxDynamicSharedMemorySize, SMB2);

    // launches 1-5 (ncu -s 5 skips these; #6 = conv GEMM is profiled)
    conv_x_k<<<65536, 256>>>((const float4*)x, (__half2*)xh);
    splitw_conv_k<<<(L_ * KCONV) / 256, 256>>>(tsn_w, wt);
    splitw_pair_k<<<512, 256>>>(aV_w, aU_w, bw);
    splitw_gen_k<<<256, 256>>>(cs_w0, 257, 65536, bw + 131072);
    splitw_gen_k<<<128, 256>>>(cs_w1, 256, 32768, bw + 196608);

    // #6: conv-as-GEMM (single fp16 pass) -> feature fp32 + fhi/flo
    mm_gemm<1, 0, 0><<<dim3(2, 128), 256, SMB1>>>(xh, nullptr, FIN, wt, KCONV,
                                                  tsn_b, nullptr, nullptr,
                                                  feat, fhi, flo, 256, KCONV);
    // fused aV|aU projection (N=512, dual bias) -> preVU
    mm_gemm<0, 4, 1><<<dim3(4, 128), 256, SMB2>>>(fhi, flo, 256, bw, 256,
                                                  aV_b, aU_b, nullptr,
                                                  preVU, nullptr, nullptr, 512, 256);
    // gated combine + softmax/bag + bag classifier
    gated_kernel<<<M_ / 8, 256>>>(preVU, gate_w, gate_b, Amat);
    softbag_kernel<<<B_, 256>>>(Amat, feat, bag, oAt);
    bagclf_kernel<<<B_ / 8, 256>>>(bag, cb_w0, cb_b0, cb_w1, cb_b1,
                                   cb_w2, cb_b2, cb_w3, cb_b3, oOut);
    // seg classifier
    mm_gemm<0, 2, 1><<<dim3(2, 128), 256, SMB2>>>(fhi, flo, 256, bw + 131072, 256,
                                                  cs_b0, Amat, cs_w0 + 256,
                                                  nullptr, h0hi, h0lo, 256, 256);
    mm_gemm<0, 3, 1><<<dim3(1, 128), 256, SMB2>>>(h0hi, h0lo, 256, bw + 196608, 256,
                                                  cs_b1, nullptr, nullptr,
                                                  h1, nullptr, nullptr, 128, 256);
    segtail_kernel<<<M_ / 8, 256>>>(h1, cs_w2, cs_b2, cs_w3, cs_b3, oSeg);
    // 2-means -> assigns + output[:,1]
    kmeans_kernel<<<B_, 256>>>(feat, oSeg, oAssign, oOut);
}